// round 8
// baseline (speedup 1.0000x reference)
#include <cuda_runtime.h>

#define BB 16
#define SS 256
#define VV 32000
#define HH 1024
#define EE 512
#define DQD 512
#define TT 255
#define KG 3584
#define G4 4096
#define XLEN 2560
#define NBLK 148

// ---------------- device scratch ----------------
__device__ __align__(16) float g_hidden[BB*SS*HH];
__device__ __align__(16) float g_hsproj[BB*SS*HH];
__device__ __align__(16) float g_h[BB*HH];
__device__ __align__(16) float g_c[BB*HH];
__device__ __align__(16) float g_h0[BB*HH];
__device__ __align__(16) float g_hW[BB*HH];
__device__ __align__(16) float g_score[BB*SS];
__device__ __align__(16) float g_gates[BB*G4];
__device__ __align__(16) float g_weighted[BB*HH];
__device__ __align__(16) float g_Wcat[(size_t)G4*KG];
__device__ __align__(16) float g_bias_sum[G4];
__device__ __align__(16) float g_we[(size_t)TT*BB*EE];
__device__ __align__(16) float g_Z[(size_t)TT*BB*2*HH];
__device__ unsigned g_cnt = 0;
__device__ volatile unsigned g_gen = 0;

__device__ __forceinline__ float fast_tanh(float x) {
    float e = __expf(2.0f * x);
    return 1.0f - __fdividef(2.0f, e + 1.0f);
}
__device__ __forceinline__ float fast_sig(float x) {
    return __fdividef(1.0f, 1.0f + __expf(-x));
}

// ---------------- prep (verbatim from verified round-3) ----------------
__global__ void k_prep(const int* __restrict__ inp, const float* __restrict__ embedW,
                       const float* __restrict__ W_ih, const float* __restrict__ W_hh,
                       const float* __restrict__ b_ih, const float* __restrict__ b_hh,
                       float* __restrict__ out)
{
    const long long N1 = (long long)G4 * KG;
    const long long N2 = N1 + G4;
    const long long N3 = N2 + (long long)TT * BB * EE;
    const long long N4 = N3 + (long long)BB * VV;
    for (long long i = (long long)blockIdx.x * blockDim.x + threadIdx.x;
         i < N4; i += (long long)gridDim.x * blockDim.x) {
        if (i < N1) {
            int n = (int)(i / KG), k = (int)(i % KG);
            g_Wcat[i] = (k < XLEN) ? W_ih[(long long)n * XLEN + k]
                                   : W_hh[(long long)n * HH + (k - XLEN)];
        } else if (i < N2) {
            int n = (int)(i - N1);
            g_bias_sum[n] = b_ih[n] + b_hh[n];
        } else if (i < N3) {
            long long j = i - N2;
            int t = (int)(j / (BB * EE));
            int r = (int)(j % (BB * EE));
            int b = r / EE, e = r % EE;
            int tok = inp[b * SS + t];
            g_we[j] = embedW[(long long)tok * EE + e];
        } else {
            long long j = i - N3;
            int b = (int)(j / VV);
            int vv = (int)(j % VV);
            out[(long long)b * SS * VV + vv] = 0.0f;
        }
    }
}

__global__ void k_init_h()
{
    int idx = blockIdx.x * blockDim.x + threadIdx.x;
    int b = idx >> 10, h = idx & 1023;
    float c0 = g_hidden[((b * SS + (SS - 1)) << 10) + h];
    g_c[idx] = c0;
    float h0 = tanhf(c0);
    g_h0[idx] = h0;
    g_h[idx] = h0;
    g_hW[idx] = 0.0f;
}

// ---------------- big tiled fp32 GEMM (verbatim from verified round-3) ----------------
template<int BIAS_EN, int SCATTER>
__global__ __launch_bounds__(256)
void k_biggemm(const float* __restrict__ A, int lda,
               const float* __restrict__ W, int ldw, int woff,
               const float* __restrict__ bias,
               float* __restrict__ C, int ldc, int M, int K)
{
    __shared__ float As[16][132];
    __shared__ float Bs[16][68];
    int tid = threadIdx.x;
    int m0 = blockIdx.x * 128;
    int n0 = blockIdx.y * 64;
    int ar  = tid >> 1;
    int akc = (tid & 1) * 8;
    int wn  = tid >> 2;
    int wkc = (tid & 3) * 4;
    int tx  = tid & 15;
    int ty  = tid >> 4;

    float acc[8][4];
#pragma unroll
    for (int i = 0; i < 8; i++)
#pragma unroll
        for (int j = 0; j < 4; j++) acc[i][j] = 0.0f;

    bool aok = (m0 + ar) < M;
    const float* Arow = A + (size_t)(m0 + ar) * lda;
    const float* Wrow = W + (size_t)(n0 + wn) * ldw + woff;

    for (int k0 = 0; k0 < K; k0 += 16) {
        float4 av0, av1;
        if (aok) {
            av0 = *(const float4*)(Arow + k0 + akc);
            av1 = *(const float4*)(Arow + k0 + akc + 4);
        } else {
            av0 = make_float4(0.f, 0.f, 0.f, 0.f);
            av1 = av0;
        }
        float4 wv = *(const float4*)(Wrow + k0 + wkc);
        __syncthreads();
        As[akc + 0][ar] = av0.x; As[akc + 1][ar] = av0.y;
        As[akc + 2][ar] = av0.z; As[akc + 3][ar] = av0.w;
        As[akc + 4][ar] = av1.x; As[akc + 5][ar] = av1.y;
        As[akc + 6][ar] = av1.z; As[akc + 7][ar] = av1.w;
        Bs[wkc + 0][wn] = wv.x;  Bs[wkc + 1][wn] = wv.y;
        Bs[wkc + 2][wn] = wv.z;  Bs[wkc + 3][wn] = wv.w;
        __syncthreads();
#pragma unroll
        for (int kk = 0; kk < 16; kk++) {
            float4 a0 = *(const float4*)&As[kk][ty * 8];
            float4 a1 = *(const float4*)&As[kk][ty * 8 + 4];
            float4 bv = *(const float4*)&Bs[kk][tx * 4];
            float ra[8] = {a0.x, a0.y, a0.z, a0.w, a1.x, a1.y, a1.z, a1.w};
            float rb[4] = {bv.x, bv.y, bv.z, bv.w};
#pragma unroll
            for (int i = 0; i < 8; i++)
#pragma unroll
                for (int j = 0; j < 4; j++)
                    acc[i][j] = fmaf(ra[i], rb[j], acc[i][j]);
        }
    }
#pragma unroll
    for (int i = 0; i < 8; i++) {
        int m = m0 + ty * 8 + i;
        if (m < M) {
            float4 r;
            r.x = acc[i][0]; r.y = acc[i][1]; r.z = acc[i][2]; r.w = acc[i][3];
            if (BIAS_EN) {
                int n = n0 + tx * 4;
                r.x += bias[n]; r.y += bias[n + 1]; r.z += bias[n + 2]; r.w += bias[n + 3];
            }
            float* dst;
            if (SCATTER) {
                int trow = m >> 4, b = m & 15;
                dst = C + (size_t)(b * SS + trow + 1) * ldc + n0 + tx * 4;
            } else {
                dst = C + (size_t)m * ldc + n0 + tx * 4;
            }
            *(float4*)dst = r;
        }
    }
}

// ---------------- persistent recurrence kernel ----------------
__device__ __forceinline__ void gbar() {
    __syncthreads();
    if (threadIdx.x == 0) {
        __threadfence();
        unsigned g = g_gen;
        if (atomicAdd(&g_cnt, 1u) == NBLK - 1) {
            g_cnt = 0;
            __threadfence();
            g_gen = g + 1;
        } else {
            while (g_gen == g) __nanosleep(64);
        }
        __threadfence();
    }
    __syncthreads();
}

__device__ __forceinline__ float gatherA_gates(int t, int b, int k)
{
    if (k < EE)        return g_we[(size_t)(t * BB + b) * EE + k];
    if (k < EE + HH)   return __ldcg(&g_weighted[(b << 10) + (k - EE)]);
    if (k < XLEN)      return g_h0[(b << 10) + (k - (EE + HH))];
    return __ldcg(&g_h[(b << 10) + (k - XLEN)]);
}

__global__ __launch_bounds__(256)
void k_recur(const float* __restrict__ attnW, const float* __restrict__ v)
{
    __shared__ float w_s[8][32][4];
    __shared__ float a_s[16][36];
    __shared__ float attn_s[SS];
    __shared__ float red_s[8];

    const int bid = blockIdx.x;
    const int tid = threadIdx.x;
    const int lane = tid & 31;
    const int wid = tid >> 5;

    for (int t = 0; t < TT; t++) {
        // ---- phase A: hW = h @ Wh^T, split-K atomics (blocks 0..127) ----
        if (bid < 128) {
            int n0 = (bid & 31) * 32;
            int kbeg = (bid >> 5) * 256;
            int n_l = tid & 31, bq = tid >> 5;
            int wn = tid >> 3, wk = (tid & 7) * 4;
            float acc0 = 0.f, acc1 = 0.f;
            for (int k0 = kbeg; k0 < kbeg + 256; k0 += 32) {
                float4 wv = *(const float4*)&attnW[(size_t)(n0 + wn) * (2 * HH) + k0 + wk];
                int kk = tid & 31, bb = tid >> 5;
                float a0 = __ldcg(&g_h[(bb << 10) + k0 + kk]);
                float a1 = __ldcg(&g_h[((bb + 8) << 10) + k0 + kk]);
                __syncthreads();
                *(float4*)&w_s[wk >> 2][wn][0] = wv;
                a_s[bq][kk] = a0;
                a_s[bq + 8][kk] = a1;
                __syncthreads();
#pragma unroll
                for (int kg = 0; kg < 8; kg++) {
                    float4 w4 = *(const float4*)&w_s[kg][n_l][0];
                    float4 A0 = *(const float4*)&a_s[bq][kg * 4];
                    float4 A1 = *(const float4*)&a_s[bq + 8][kg * 4];
                    acc0 = fmaf(w4.x, A0.x, acc0); acc0 = fmaf(w4.y, A0.y, acc0);
                    acc0 = fmaf(w4.z, A0.z, acc0); acc0 = fmaf(w4.w, A0.w, acc0);
                    acc1 = fmaf(w4.x, A1.x, acc1); acc1 = fmaf(w4.y, A1.y, acc1);
                    acc1 = fmaf(w4.z, A1.z, acc1); acc1 = fmaf(w4.w, A1.w, acc1);
                }
            }
            atomicAdd(&g_hW[(bq << 10) + n0 + n_l], acc0);
            atomicAdd(&g_hW[((bq + 8) << 10) + n0 + n_l], acc1);
        }
        gbar();

        // ---- phase B: scores (all blocks, warp per (b,s) pair) ----
        for (int p = bid * 8 + wid; p < BB * SS; p += NBLK * 8) {
            int b = p >> 8, s = p & 255;
            const float* hsp = g_hsproj + ((size_t)(b * SS + s) << 10);
            const float* hw = g_hW + (b << 10);
            float acc = 0.f;
#pragma unroll 8
            for (int i = 0; i < 32; i++) {
                int k = lane + (i << 5);
                acc += v[k] * fast_tanh(__ldcg(&hw[k]) + hsp[k]);
            }
#pragma unroll
            for (int o = 16; o > 0; o >>= 1) acc += __shfl_xor_sync(0xffffffffu, acc, o);
            if (lane == 0) g_score[p] = acc;
        }
        gbar();

        // ---- phase C: softmax + weighted (blocks 0..63) ----
        if (bid < 64) {
            int b = bid >> 2;
            int hbase = (bid & 3) * 256;
            float sc = __ldcg(&g_score[b * SS + tid]);
            float m = sc;
#pragma unroll
            for (int o = 16; o > 0; o >>= 1) m = fmaxf(m, __shfl_xor_sync(0xffffffffu, m, o));
            if (lane == 0) red_s[wid] = m;
            __syncthreads();
            m = red_s[0];
#pragma unroll
            for (int w = 1; w < 8; w++) m = fmaxf(m, red_s[w]);
            float e = __expf(sc - m);
            float sum = e;
#pragma unroll
            for (int o = 16; o > 0; o >>= 1) sum += __shfl_xor_sync(0xffffffffu, sum, o);
            __syncthreads();
            attn_s[tid] = e;
            if (lane == 0) red_s[wid] = sum;
            __syncthreads();
            sum = 0.f;
#pragma unroll
            for (int w = 0; w < 8; w++) sum += red_s[w];
            float inv = __fdividef(1.0f, sum);

            int h = hbase + tid;
            const float* hv = g_hidden + ((size_t)(b * SS) << 10) + h;
            float a0 = 0.f, a1 = 0.f, a2 = 0.f, a3 = 0.f;
            for (int s = 0; s < SS; s += 4) {
                a0 = fmaf(attn_s[s],     hv[(size_t)s << 10],       a0);
                a1 = fmaf(attn_s[s + 1], hv[(size_t)(s + 1) << 10], a1);
                a2 = fmaf(attn_s[s + 2], hv[(size_t)(s + 2) << 10], a2);
                a3 = fmaf(attn_s[s + 3], hv[(size_t)(s + 3) << 10], a3);
            }
            float acc = ((a0 + a1) + (a2 + a3)) * inv;
            g_weighted[(b << 10) + h] = acc;
            g_Z[((size_t)(t * BB + b) << 11) + HH + h] = acc;
        }
        gbar();

        // ---- phase D: gates (blocks 0..127) ----
        if (bid < 128) {
            int n0 = bid * 32;
            int n_l = tid & 31, bq = tid >> 5;
            int wn = tid >> 3, wk = (tid & 7) * 4;
            float acc0 = 0.f, acc1 = 0.f;
            for (int k0 = 0; k0 < KG; k0 += 32) {
                float4 wv = *(const float4*)&g_Wcat[(size_t)(n0 + wn) * KG + k0 + wk];
                int kk = tid & 31, bb = tid >> 5;
                float a0 = gatherA_gates(t, bb, k0 + kk);
                float a1 = gatherA_gates(t, bb + 8, k0 + kk);
                __syncthreads();
                *(float4*)&w_s[wk >> 2][wn][0] = wv;
                a_s[bq][kk] = a0;
                a_s[bq + 8][kk] = a1;
                __syncthreads();
#pragma unroll
                for (int kg = 0; kg < 8; kg++) {
                    float4 w4 = *(const float4*)&w_s[kg][n_l][0];
                    float4 A0 = *(const float4*)&a_s[bq][kg * 4];
                    float4 A1 = *(const float4*)&a_s[bq + 8][kg * 4];
                    acc0 = fmaf(w4.x, A0.x, acc0); acc0 = fmaf(w4.y, A0.y, acc0);
                    acc0 = fmaf(w4.z, A0.z, acc0); acc0 = fmaf(w4.w, A0.w, acc0);
                    acc1 = fmaf(w4.x, A1.x, acc1); acc1 = fmaf(w4.y, A1.y, acc1);
                    acc1 = fmaf(w4.z, A1.z, acc1); acc1 = fmaf(w4.w, A1.w, acc1);
                }
            }
            float bsum = g_bias_sum[n0 + n_l];
            g_gates[bq * G4 + n0 + n_l]       = acc0 + bsum;
            g_gates[(bq + 8) * G4 + n0 + n_l] = acc1 + bsum;
        }
        gbar();

        // ---- phase E: LSTM cell (blocks 0..63) ----
        if (bid < 64) {
            int idx = (bid << 8) + tid;
            int b = idx >> 10, h = idx & 1023;
            const float* g = g_gates + b * G4;
            float ig = __ldcg(&g[h]);
            float fg = __ldcg(&g[HH + h]);
            float gg = __ldcg(&g[2 * HH + h]);
            float og = __ldcg(&g[3 * HH + h]);
            float c = fast_sig(fg) * g_c[idx] + fast_sig(ig) * fast_tanh(gg);
            float hn = fast_sig(og) * fast_tanh(c);
            g_c[idx] = c;
            g_h[idx] = hn;
            g_Z[((size_t)(t * BB + b) << 11) + h] = hn;
            g_hW[idx] = 0.0f;
        }
        gbar();
    }
}

// ---------------- host launch ----------------
extern "C" void kernel_launch(void* const* d_in, const int* in_sizes, int n_in,
                              void* d_out, int out_size)
{
    (void)in_sizes; (void)n_in; (void)out_size;
    const int*   inp    = (const int*)  d_in[0];
    const float* VQ     = (const float*)d_in[1];
    const float* embedW = (const float*)d_in[2];
    const float* transW = (const float*)d_in[3];
    const float* attnW  = (const float*)d_in[4];
    const float* attnb  = (const float*)d_in[5];
    const float* v      = (const float*)d_in[6];
    const float* W_ih   = (const float*)d_in[7];
    const float* W_hh   = (const float*)d_in[8];
    const float* b_ih   = (const float*)d_in[9];
    const float* b_hh   = (const float*)d_in[10];
    const float* predW  = (const float*)d_in[11];
    float* out = (float*)d_out;

    float *p_hidden, *p_hsproj, *p_Z;
    cudaGetSymbolAddress((void**)&p_hidden, g_hidden);
    cudaGetSymbolAddress((void**)&p_hsproj, g_hsproj);
    cudaGetSymbolAddress((void**)&p_Z,      g_Z);

    k_prep<<<2048, 256>>>(inp, embedW, W_ih, W_hh, b_ih, b_hh, out);
    k_biggemm<0, 0><<<dim3(32, 16), 256>>>(VQ, DQD, transW, DQD, 0, nullptr,
                                           p_hidden, HH, BB * SS, DQD);
    k_biggemm<1, 0><<<dim3(32, 16), 256>>>(p_hidden, HH, attnW, 2 * HH, HH, attnb,
                                           p_hsproj, HH, BB * SS, HH);
    k_init_h<<<64, 256>>>();

    // entire 255-step recurrence: ONE kernel, software grid barrier
    k_recur<<<NBLK, 256>>>(attnW, v);

    // hoisted logits GEMM (4080 x 32000, K=2048)
    k_biggemm<0, 1><<<dim3(32, 500), 256>>>(p_Z, 2 * HH, predW, 2 * HH, 0, nullptr,
                                            out, VV, TT * BB, 2 * HH);
}

// round 9
// speedup vs baseline: 1.0493x; 1.0493x over previous
#include <cuda_runtime.h>

#define BB 16
#define SS 256
#define VV 32000
#define HH 1024
#define EE 512
#define DQD 512
#define TT 255
#define KG 3584
#define G4 4096
#define XLEN 2560
#define NBLK 148

// ---------------- device scratch ----------------
__device__ __align__(16) float g_hidden[BB*SS*HH];
__device__ __align__(16) float g_hsproj[BB*SS*HH];
__device__ __align__(16) float g_h[BB*HH];
__device__ __align__(16) float g_c[BB*HH];
__device__ __align__(16) float g_h0[BB*HH];
__device__ __align__(16) float g_hW[BB*HH];
__device__ __align__(16) float g_score[BB*SS];
__device__ __align__(16) float g_gates[BB*G4];
__device__ __align__(16) float g_weighted[BB*HH];
__device__ __align__(16) float g_Wcat[(size_t)G4*KG];
__device__ __align__(16) float g_bias_sum[G4];
__device__ __align__(16) float g_we[(size_t)TT*BB*EE];
__device__ __align__(16) float g_Z[(size_t)TT*BB*2*HH];
__device__ unsigned g_cnt = 0;
__device__ volatile unsigned g_gen = 0;

__device__ __forceinline__ float fast_tanh(float x) {
    float e = __expf(2.0f * x);
    return 1.0f - __fdividef(2.0f, e + 1.0f);
}
__device__ __forceinline__ float fast_sig(float x) {
    return __fdividef(1.0f, 1.0f + __expf(-x));
}

// ---------------- prep (verbatim from verified round-3) ----------------
__global__ void k_prep(const int* __restrict__ inp, const float* __restrict__ embedW,
                       const float* __restrict__ W_ih, const float* __restrict__ W_hh,
                       const float* __restrict__ b_ih, const float* __restrict__ b_hh,
                       float* __restrict__ out)
{
    const long long N1 = (long long)G4 * KG;
    const long long N2 = N1 + G4;
    const long long N3 = N2 + (long long)TT * BB * EE;
    const long long N4 = N3 + (long long)BB * VV;
    for (long long i = (long long)blockIdx.x * blockDim.x + threadIdx.x;
         i < N4; i += (long long)gridDim.x * blockDim.x) {
        if (i < N1) {
            int n = (int)(i / KG), k = (int)(i % KG);
            g_Wcat[i] = (k < XLEN) ? W_ih[(long long)n * XLEN + k]
                                   : W_hh[(long long)n * HH + (k - XLEN)];
        } else if (i < N2) {
            int n = (int)(i - N1);
            g_bias_sum[n] = b_ih[n] + b_hh[n];
        } else if (i < N3) {
            long long j = i - N2;
            int t = (int)(j / (BB * EE));
            int r = (int)(j % (BB * EE));
            int b = r / EE, e = r % EE;
            int tok = inp[b * SS + t];
            g_we[j] = embedW[(long long)tok * EE + e];
        } else {
            long long j = i - N3;
            int b = (int)(j / VV);
            int vv = (int)(j % VV);
            out[(long long)b * SS * VV + vv] = 0.0f;
        }
    }
}

__global__ void k_init_h()
{
    int idx = blockIdx.x * blockDim.x + threadIdx.x;
    int b = idx >> 10, h = idx & 1023;
    float c0 = g_hidden[((b * SS + (SS - 1)) << 10) + h];
    g_c[idx] = c0;
    float h0 = tanhf(c0);
    g_h0[idx] = h0;
    g_h[idx] = h0;
    g_hW[idx] = 0.0f;
}

// ---------------- big tiled fp32 GEMM (verbatim from verified round-3) ----------------
template<int BIAS_EN, int SCATTER>
__global__ __launch_bounds__(256)
void k_biggemm(const float* __restrict__ A, int lda,
               const float* __restrict__ W, int ldw, int woff,
               const float* __restrict__ bias,
               float* __restrict__ C, int ldc, int M, int K)
{
    __shared__ float As[16][132];
    __shared__ float Bs[16][68];
    int tid = threadIdx.x;
    int m0 = blockIdx.x * 128;
    int n0 = blockIdx.y * 64;
    int ar  = tid >> 1;
    int akc = (tid & 1) * 8;
    int wn  = tid >> 2;
    int wkc = (tid & 3) * 4;
    int tx  = tid & 15;
    int ty  = tid >> 4;

    float acc[8][4];
#pragma unroll
    for (int i = 0; i < 8; i++)
#pragma unroll
        for (int j = 0; j < 4; j++) acc[i][j] = 0.0f;

    bool aok = (m0 + ar) < M;
    const float* Arow = A + (size_t)(m0 + ar) * lda;
    const float* Wrow = W + (size_t)(n0 + wn) * ldw + woff;

    for (int k0 = 0; k0 < K; k0 += 16) {
        float4 av0, av1;
        if (aok) {
            av0 = *(const float4*)(Arow + k0 + akc);
            av1 = *(const float4*)(Arow + k0 + akc + 4);
        } else {
            av0 = make_float4(0.f, 0.f, 0.f, 0.f);
            av1 = av0;
        }
        float4 wv = *(const float4*)(Wrow + k0 + wkc);
        __syncthreads();
        As[akc + 0][ar] = av0.x; As[akc + 1][ar] = av0.y;
        As[akc + 2][ar] = av0.z; As[akc + 3][ar] = av0.w;
        As[akc + 4][ar] = av1.x; As[akc + 5][ar] = av1.y;
        As[akc + 6][ar] = av1.z; As[akc + 7][ar] = av1.w;
        Bs[wkc + 0][wn] = wv.x;  Bs[wkc + 1][wn] = wv.y;
        Bs[wkc + 2][wn] = wv.z;  Bs[wkc + 3][wn] = wv.w;
        __syncthreads();
#pragma unroll
        for (int kk = 0; kk < 16; kk++) {
            float4 a0 = *(const float4*)&As[kk][ty * 8];
            float4 a1 = *(const float4*)&As[kk][ty * 8 + 4];
            float4 bv = *(const float4*)&Bs[kk][tx * 4];
            float ra[8] = {a0.x, a0.y, a0.z, a0.w, a1.x, a1.y, a1.z, a1.w};
            float rb[4] = {bv.x, bv.y, bv.z, bv.w};
#pragma unroll
            for (int i = 0; i < 8; i++)
#pragma unroll
                for (int j = 0; j < 4; j++)
                    acc[i][j] = fmaf(ra[i], rb[j], acc[i][j]);
        }
    }
#pragma unroll
    for (int i = 0; i < 8; i++) {
        int m = m0 + ty * 8 + i;
        if (m < M) {
            float4 r;
            r.x = acc[i][0]; r.y = acc[i][1]; r.z = acc[i][2]; r.w = acc[i][3];
            if (BIAS_EN) {
                int n = n0 + tx * 4;
                r.x += bias[n]; r.y += bias[n + 1]; r.z += bias[n + 2]; r.w += bias[n + 3];
            }
            float* dst;
            if (SCATTER) {
                int trow = m >> 4, b = m & 15;
                dst = C + (size_t)(b * SS + trow + 1) * ldc + n0 + tx * 4;
            } else {
                dst = C + (size_t)m * ldc + n0 + tx * 4;
            }
            *(float4*)dst = r;
        }
    }
}

// ---------------- persistent recurrence kernel ----------------
__device__ __forceinline__ void gbar() {
    __syncthreads();
    if (threadIdx.x == 0) {
        __threadfence();
        unsigned g = g_gen;
        if (atomicAdd(&g_cnt, 1u) == NBLK - 1) {
            g_cnt = 0;
            __threadfence();
            g_gen = g + 1;
        } else {
            while (g_gen == g) __nanosleep(64);
        }
        __threadfence();
    }
    __syncthreads();
}

__device__ __forceinline__ float gatherA_gates(int t, int b, int k)
{
    if (k < EE)        return g_we[(size_t)(t * BB + b) * EE + k];
    if (k < EE + HH)   return __ldcg(&g_weighted[(b << 10) + (k - EE)]);
    if (k < XLEN)      return g_h0[(b << 10) + (k - (EE + HH))];
    return __ldcg(&g_h[(b << 10) + (k - XLEN)]);
}

__global__ __launch_bounds__(256)
void k_recur(const float* __restrict__ attnW, const float* __restrict__ v)
{
    __shared__ float w_s[8][32][4];
    __shared__ float a_s[16][36];
    __shared__ float attn_s[SS];
    __shared__ float red_s[8];

    const int bid = blockIdx.x;
    const int tid = threadIdx.x;
    const int lane = tid & 31;
    const int wid = tid >> 5;

    for (int t = 0; t < TT; t++) {
        // ---- phase A: hW = h @ Wh^T, split-K atomics (blocks 0..127) ----
        if (bid < 128) {
            int n0 = (bid & 31) * 32;
            int kbeg = (bid >> 5) * 256;
            int n_l = tid & 31, bq = tid >> 5;
            int wn = tid >> 3, wk = (tid & 7) * 4;
            float acc0 = 0.f, acc1 = 0.f;
            for (int k0 = kbeg; k0 < kbeg + 256; k0 += 32) {
                float4 wv = *(const float4*)&attnW[(size_t)(n0 + wn) * (2 * HH) + k0 + wk];
                int kk = tid & 31, bb = tid >> 5;
                float a0 = __ldcg(&g_h[(bb << 10) + k0 + kk]);
                float a1 = __ldcg(&g_h[((bb + 8) << 10) + k0 + kk]);
                __syncthreads();
                *(float4*)&w_s[wk >> 2][wn][0] = wv;
                a_s[bq][kk] = a0;
                a_s[bq + 8][kk] = a1;
                __syncthreads();
#pragma unroll
                for (int kg = 0; kg < 8; kg++) {
                    float4 w4 = *(const float4*)&w_s[kg][n_l][0];
                    float4 A0 = *(const float4*)&a_s[bq][kg * 4];
                    float4 A1 = *(const float4*)&a_s[bq + 8][kg * 4];
                    acc0 = fmaf(w4.x, A0.x, acc0); acc0 = fmaf(w4.y, A0.y, acc0);
                    acc0 = fmaf(w4.z, A0.z, acc0); acc0 = fmaf(w4.w, A0.w, acc0);
                    acc1 = fmaf(w4.x, A1.x, acc1); acc1 = fmaf(w4.y, A1.y, acc1);
                    acc1 = fmaf(w4.z, A1.z, acc1); acc1 = fmaf(w4.w, A1.w, acc1);
                }
            }
            atomicAdd(&g_hW[(bq << 10) + n0 + n_l], acc0);
            atomicAdd(&g_hW[((bq + 8) << 10) + n0 + n_l], acc1);
        }
        gbar();

        // ---- phase B: scores (all blocks, warp per (b,s) pair) ----
        for (int p = bid * 8 + wid; p < BB * SS; p += NBLK * 8) {
            int b = p >> 8, s = p & 255;
            const float* hsp = g_hsproj + ((size_t)(b * SS + s) << 10);
            const float* hw = g_hW + (b << 10);
            float acc = 0.f;
#pragma unroll 8
            for (int i = 0; i < 32; i++) {
                int k = lane + (i << 5);
                acc += v[k] * fast_tanh(__ldcg(&hw[k]) + hsp[k]);
            }
#pragma unroll
            for (int o = 16; o > 0; o >>= 1) acc += __shfl_xor_sync(0xffffffffu, acc, o);
            if (lane == 0) g_score[p] = acc;
        }
        gbar();

        // ---- phase C: softmax + weighted (blocks 0..63) ----
        if (bid < 64) {
            int b = bid >> 2;
            int hbase = (bid & 3) * 256;
            float sc = __ldcg(&g_score[b * SS + tid]);
            float m = sc;
#pragma unroll
            for (int o = 16; o > 0; o >>= 1) m = fmaxf(m, __shfl_xor_sync(0xffffffffu, m, o));
            if (lane == 0) red_s[wid] = m;
            __syncthreads();
            m = red_s[0];
#pragma unroll
            for (int w = 1; w < 8; w++) m = fmaxf(m, red_s[w]);
            float e = __expf(sc - m);
            float sum = e;
#pragma unroll
            for (int o = 16; o > 0; o >>= 1) sum += __shfl_xor_sync(0xffffffffu, sum, o);
            __syncthreads();
            attn_s[tid] = e;
            if (lane == 0) red_s[wid] = sum;
            __syncthreads();
            sum = 0.f;
#pragma unroll
            for (int w = 0; w < 8; w++) sum += red_s[w];
            float inv = __fdividef(1.0f, sum);

            int h = hbase + tid;
            const float* hv = g_hidden + ((size_t)(b * SS) << 10) + h;
            float a0 = 0.f, a1 = 0.f, a2 = 0.f, a3 = 0.f;
            for (int s = 0; s < SS; s += 4) {
                a0 = fmaf(attn_s[s],     hv[(size_t)s << 10],       a0);
                a1 = fmaf(attn_s[s + 1], hv[(size_t)(s + 1) << 10], a1);
                a2 = fmaf(attn_s[s + 2], hv[(size_t)(s + 2) << 10], a2);
                a3 = fmaf(attn_s[s + 3], hv[(size_t)(s + 3) << 10], a3);
            }
            float acc = ((a0 + a1) + (a2 + a3)) * inv;
            g_weighted[(b << 10) + h] = acc;
            g_Z[((size_t)(t * BB + b) << 11) + HH + h] = acc;
        }
        gbar();

        // ---- phase D: gates (blocks 0..127) ----
        if (bid < 128) {
            int n0 = bid * 32;
            int n_l = tid & 31, bq = tid >> 5;
            int wn = tid >> 3, wk = (tid & 7) * 4;
            float acc0 = 0.f, acc1 = 0.f;
            for (int k0 = 0; k0 < KG; k0 += 32) {
                float4 wv = *(const float4*)&g_Wcat[(size_t)(n0 + wn) * KG + k0 + wk];
                int kk = tid & 31, bb = tid >> 5;
                float a0 = gatherA_gates(t, bb, k0 + kk);
                float a1 = gatherA_gates(t, bb + 8, k0 + kk);
                __syncthreads();
                *(float4*)&w_s[wk >> 2][wn][0] = wv;
                a_s[bq][kk] = a0;
                a_s[bq + 8][kk] = a1;
                __syncthreads();
#pragma unroll
                for (int kg = 0; kg < 8; kg++) {
                    float4 w4 = *(const float4*)&w_s[kg][n_l][0];
                    float4 A0 = *(const float4*)&a_s[bq][kg * 4];
                    float4 A1 = *(const float4*)&a_s[bq + 8][kg * 4];
                    acc0 = fmaf(w4.x, A0.x, acc0); acc0 = fmaf(w4.y, A0.y, acc0);
                    acc0 = fmaf(w4.z, A0.z, acc0); acc0 = fmaf(w4.w, A0.w, acc0);
                    acc1 = fmaf(w4.x, A1.x, acc1); acc1 = fmaf(w4.y, A1.y, acc1);
                    acc1 = fmaf(w4.z, A1.z, acc1); acc1 = fmaf(w4.w, A1.w, acc1);
                }
            }
            float bsum = g_bias_sum[n0 + n_l];
            g_gates[bq * G4 + n0 + n_l]       = acc0 + bsum;
            g_gates[(bq + 8) * G4 + n0 + n_l] = acc1 + bsum;
        }
        gbar();

        // ---- phase E: LSTM cell (blocks 0..63) ----
        if (bid < 64) {
            int idx = (bid << 8) + tid;
            int b = idx >> 10, h = idx & 1023;
            const float* g = g_gates + b * G4;
            float ig = __ldcg(&g[h]);
            float fg = __ldcg(&g[HH + h]);
            float gg = __ldcg(&g[2 * HH + h]);
            float og = __ldcg(&g[3 * HH + h]);
            float c = fast_sig(fg) * g_c[idx] + fast_sig(ig) * fast_tanh(gg);
            float hn = fast_sig(og) * fast_tanh(c);
            g_c[idx] = c;
            g_h[idx] = hn;
            g_Z[((size_t)(t * BB + b) << 11) + h] = hn;
            g_hW[idx] = 0.0f;
        }
        gbar();
    }
}

// ---------------- host launch ----------------
extern "C" void kernel_launch(void* const* d_in, const int* in_sizes, int n_in,
                              void* d_out, int out_size)
{
    (void)in_sizes; (void)n_in; (void)out_size;
    const int*   inp    = (const int*)  d_in[0];
    const float* VQ     = (const float*)d_in[1];
    const float* embedW = (const float*)d_in[2];
    const float* transW = (const float*)d_in[3];
    const float* attnW  = (const float*)d_in[4];
    const float* attnb  = (const float*)d_in[5];
    const float* v      = (const float*)d_in[6];
    const float* W_ih   = (const float*)d_in[7];
    const float* W_hh   = (const float*)d_in[8];
    const float* b_ih   = (const float*)d_in[9];
    const float* b_hh   = (const float*)d_in[10];
    const float* predW  = (const float*)d_in[11];
    float* out = (float*)d_out;

    float *p_hidden, *p_hsproj, *p_Z;
    cudaGetSymbolAddress((void**)&p_hidden, g_hidden);
    cudaGetSymbolAddress((void**)&p_hsproj, g_hsproj);
    cudaGetSymbolAddress((void**)&p_Z,      g_Z);

    k_prep<<<2048, 256>>>(inp, embedW, W_ih, W_hh, b_ih, b_hh, out);
    k_biggemm<0, 0><<<dim3(32, 16), 256>>>(VQ, DQD, transW, DQD, 0, nullptr,
                                           p_hidden, HH, BB * SS, DQD);
    k_biggemm<1, 0><<<dim3(32, 16), 256>>>(p_hidden, HH, attnW, 2 * HH, HH, attnb,
                                           p_hsproj, HH, BB * SS, HH);
    k_init_h<<<64, 256>>>();

    // entire 255-step recurrence: ONE kernel, software grid barrier
    k_recur<<<NBLK, 256>>>(attnW, v);

    // hoisted logits GEMM (4080 x 32000, K=2048)
    k_biggemm<0, 1><<<dim3(32, 500), 256>>>(p_Z, 2 * HH, predW, 2 * HH, 0, nullptr,
                                            out, VV, TT * BB, 2 * HH);
}

// round 10
// speedup vs baseline: 1.2887x; 1.2281x over previous
#include <cuda_runtime.h>

#define BB 16
#define SS 256
#define VV 32000
#define HH 1024
#define EE 512
#define DQD 512
#define TT 255
#define KG 3584
#define G4 4096
#define XLEN 2560
#define NBLK 148

typedef unsigned long long ull;

// ---------------- device scratch ----------------
__device__ __align__(16) float g_hidden[BB*SS*HH];
__device__ __align__(16) float g_hsproj[BB*SS*HH];
__device__ __align__(16) float g_h[BB*HH];
__device__ __align__(16) float g_c[BB*HH];
__device__ __align__(16) float g_h0[BB*HH];
__device__ __align__(16) float g_hW[BB*HH];
__device__ __align__(16) float g_score[BB*SS];
__device__ __align__(16) float g_gates[BB*G4];
__device__ __align__(16) float g_weighted[BB*HH];
__device__ __align__(16) float g_Wcat[(size_t)G4*KG];
__device__ __align__(16) float g_bias_sum[G4];
__device__ __align__(16) float g_we[(size_t)TT*BB*EE];
__device__ __align__(16) float g_Z[(size_t)TT*BB*2*HH];
__device__ unsigned g_cnt = 0;
__device__ volatile unsigned g_gen = 0;

// ---------------- f32x2 helpers (exact fp32 pairs, dual-rate FMA) ----------------
__device__ __forceinline__ void ffma2(ull& d, ull a, ull b) {
    asm("fma.rn.f32x2 %0, %1, %2, %0;" : "+l"(d) : "l"(a), "l"(b));
}
__device__ __forceinline__ ull dup2(float x) {
    ull r; asm("mov.b64 %0, {%1, %1};" : "=l"(r) : "f"(x)); return r;
}
__device__ __forceinline__ float2 up2(ull u) {
    float2 f; asm("mov.b64 {%0, %1}, %2;" : "=f"(f.x), "=f"(f.y) : "l"(u)); return f;
}

__device__ __forceinline__ float fast_tanh(float x) {
    float e = __expf(2.0f * x);
    return 1.0f - __fdividef(2.0f, e + 1.0f);
}
__device__ __forceinline__ float fast_sig(float x) {
    return __fdividef(1.0f, 1.0f + __expf(-x));
}

// ---------------- prep (verbatim, verified) ----------------
__global__ void k_prep(const int* __restrict__ inp, const float* __restrict__ embedW,
                       const float* __restrict__ W_ih, const float* __restrict__ W_hh,
                       const float* __restrict__ b_ih, const float* __restrict__ b_hh,
                       float* __restrict__ out)
{
    const long long N1 = (long long)G4 * KG;
    const long long N2 = N1 + G4;
    const long long N3 = N2 + (long long)TT * BB * EE;
    const long long N4 = N3 + (long long)BB * VV;
    for (long long i = (long long)blockIdx.x * blockDim.x + threadIdx.x;
         i < N4; i += (long long)gridDim.x * blockDim.x) {
        if (i < N1) {
            int n = (int)(i / KG), k = (int)(i % KG);
            g_Wcat[i] = (k < XLEN) ? W_ih[(long long)n * XLEN + k]
                                   : W_hh[(long long)n * HH + (k - XLEN)];
        } else if (i < N2) {
            int n = (int)(i - N1);
            g_bias_sum[n] = b_ih[n] + b_hh[n];
        } else if (i < N3) {
            long long j = i - N2;
            int t = (int)(j / (BB * EE));
            int r = (int)(j % (BB * EE));
            int b = r / EE, e = r % EE;
            int tok = inp[b * SS + t];
            g_we[j] = embedW[(long long)tok * EE + e];
        } else {
            long long j = i - N3;
            int b = (int)(j / VV);
            int vv = (int)(j % VV);
            out[(long long)b * SS * VV + vv] = 0.0f;
        }
    }
}

__global__ void k_init_h()
{
    int idx = blockIdx.x * blockDim.x + threadIdx.x;
    int b = idx >> 10, h = idx & 1023;
    float c0 = g_hidden[((b * SS + (SS - 1)) << 10) + h];
    g_c[idx] = c0;
    float h0 = tanhf(c0);
    g_h0[idx] = h0;
    g_h[idx] = h0;
    g_hW[idx] = 0.0f;
}

// ---------------- big tiled fp32 GEMM (verified; precompute only) ----------------
template<int BIAS_EN>
__global__ __launch_bounds__(256)
void k_biggemm(const float* __restrict__ A, int lda,
               const float* __restrict__ W, int ldw, int woff,
               const float* __restrict__ bias,
               float* __restrict__ C, int ldc, int M, int K)
{
    __shared__ float As[16][132];
    __shared__ float Bs[16][68];
    int tid = threadIdx.x;
    int m0 = blockIdx.x * 128;
    int n0 = blockIdx.y * 64;
    int ar  = tid >> 1;
    int akc = (tid & 1) * 8;
    int wn  = tid >> 2;
    int wkc = (tid & 3) * 4;
    int tx  = tid & 15;
    int ty  = tid >> 4;

    float acc[8][4];
#pragma unroll
    for (int i = 0; i < 8; i++)
#pragma unroll
        for (int j = 0; j < 4; j++) acc[i][j] = 0.0f;

    const float* Arow = A + (size_t)(m0 + ar) * lda;
    const float* Wrow = W + (size_t)(n0 + wn) * ldw + woff;

    for (int k0 = 0; k0 < K; k0 += 16) {
        float4 av0 = *(const float4*)(Arow + k0 + akc);
        float4 av1 = *(const float4*)(Arow + k0 + akc + 4);
        float4 wv  = *(const float4*)(Wrow + k0 + wkc);
        __syncthreads();
        As[akc + 0][ar] = av0.x; As[akc + 1][ar] = av0.y;
        As[akc + 2][ar] = av0.z; As[akc + 3][ar] = av0.w;
        As[akc + 4][ar] = av1.x; As[akc + 5][ar] = av1.y;
        As[akc + 6][ar] = av1.z; As[akc + 7][ar] = av1.w;
        Bs[wkc + 0][wn] = wv.x;  Bs[wkc + 1][wn] = wv.y;
        Bs[wkc + 2][wn] = wv.z;  Bs[wkc + 3][wn] = wv.w;
        __syncthreads();
#pragma unroll
        for (int kk = 0; kk < 16; kk++) {
            float4 a0 = *(const float4*)&As[kk][ty * 8];
            float4 a1 = *(const float4*)&As[kk][ty * 8 + 4];
            float4 bv = *(const float4*)&Bs[kk][tx * 4];
            float ra[8] = {a0.x, a0.y, a0.z, a0.w, a1.x, a1.y, a1.z, a1.w};
            float rb[4] = {bv.x, bv.y, bv.z, bv.w};
#pragma unroll
            for (int i = 0; i < 8; i++)
#pragma unroll
                for (int j = 0; j < 4; j++)
                    acc[i][j] = fmaf(ra[i], rb[j], acc[i][j]);
        }
    }
#pragma unroll
    for (int i = 0; i < 8; i++) {
        int m = m0 + ty * 8 + i;
        float4 r;
        r.x = acc[i][0]; r.y = acc[i][1]; r.z = acc[i][2]; r.w = acc[i][3];
        if (BIAS_EN) {
            int n = n0 + tx * 4;
            r.x += bias[n]; r.y += bias[n + 1]; r.z += bias[n + 2]; r.w += bias[n + 3];
        }
        *(float4*)(C + (size_t)m * ldc + n0 + tx * 4) = r;
    }
}

// ---------------- logits GEMM: f32x2, 128x128x16 tiles, scatter epilogue ----------------
// C[b*SS + t+1][n] = sum_k Z[m][k] * predW[n][k],  m = t*16 + b
__global__ __launch_bounds__(256)
void k_logits(const float* __restrict__ A, const float* __restrict__ W,
              float* __restrict__ C)
{
    __shared__ float As[16][132];
    __shared__ float Bs[16][132];
    int tid = threadIdx.x;
    int m0 = blockIdx.x * 128;
    int n0 = blockIdx.y * 128;
    int r  = tid >> 1;
    int kc = (tid & 1) * 8;
    int tx = tid & 15;
    int ty = tid >> 4;

    ull acc[8][4];
#pragma unroll
    for (int i = 0; i < 8; i++)
#pragma unroll
        for (int j = 0; j < 4; j++) acc[i][j] = 0ull;

    bool aok = (m0 + r) < (TT * BB);
    const float* Arow = A + (size_t)(m0 + r) * (2 * HH);
    const float* Wrow = W + (size_t)(n0 + r) * (2 * HH);

    float4 av0, av1, bv0, bv1;
    if (aok) {
        av0 = *(const float4*)(Arow + kc);
        av1 = *(const float4*)(Arow + kc + 4);
    } else { av0 = make_float4(0.f,0.f,0.f,0.f); av1 = av0; }
    bv0 = *(const float4*)(Wrow + kc);
    bv1 = *(const float4*)(Wrow + kc + 4);

    for (int k0 = 0; k0 < 2 * HH; k0 += 16) {
        __syncthreads();
        As[kc + 0][r] = av0.x; As[kc + 1][r] = av0.y;
        As[kc + 2][r] = av0.z; As[kc + 3][r] = av0.w;
        As[kc + 4][r] = av1.x; As[kc + 5][r] = av1.y;
        As[kc + 6][r] = av1.z; As[kc + 7][r] = av1.w;
        Bs[kc + 0][r] = bv0.x; Bs[kc + 1][r] = bv0.y;
        Bs[kc + 2][r] = bv0.z; Bs[kc + 3][r] = bv0.w;
        Bs[kc + 4][r] = bv1.x; Bs[kc + 5][r] = bv1.y;
        Bs[kc + 6][r] = bv1.z; Bs[kc + 7][r] = bv1.w;
        __syncthreads();
        int kn = k0 + 16;
        if (kn < 2 * HH) {
            if (aok) {
                av0 = *(const float4*)(Arow + kn + kc);
                av1 = *(const float4*)(Arow + kn + kc + 4);
            }
            bv0 = *(const float4*)(Wrow + kn + kc);
            bv1 = *(const float4*)(Wrow + kn + kc + 4);
        }
#pragma unroll
        for (int kk = 0; kk < 16; kk++) {
            float4 a0 = *(const float4*)&As[kk][ty * 8];
            float4 a1 = *(const float4*)&As[kk][ty * 8 + 4];
            ull b0 = *(const ull*)&Bs[kk][tx * 4];
            ull b1 = *(const ull*)&Bs[kk][tx * 4 + 2];
            ull b2 = *(const ull*)&Bs[kk][64 + tx * 4];
            ull b3 = *(const ull*)&Bs[kk][64 + tx * 4 + 2];
            float aa[8] = {a0.x, a0.y, a0.z, a0.w, a1.x, a1.y, a1.z, a1.w};
#pragma unroll
            for (int i = 0; i < 8; i++) {
                ull ad = dup2(aa[i]);
                ffma2(acc[i][0], ad, b0);
                ffma2(acc[i][1], ad, b1);
                ffma2(acc[i][2], ad, b2);
                ffma2(acc[i][3], ad, b3);
            }
        }
    }
#pragma unroll
    for (int i = 0; i < 8; i++) {
        int m = m0 + ty * 8 + i;
        if (m < TT * BB) {
            int trow = m >> 4, b = m & 15;
            float* dst = C + (size_t)(b * SS + trow + 1) * VV + n0 + tx * 4;
            float2 v0 = up2(acc[i][0]), v1 = up2(acc[i][1]);
            float2 v2 = up2(acc[i][2]), v3 = up2(acc[i][3]);
            float4 w0 = {v0.x, v0.y, v1.x, v1.y};
            float4 w1 = {v2.x, v2.y, v3.x, v3.y};
            *(float4*)dst = w0;
            *(float4*)(dst + 64) = w1;
        }
    }
}

// ---------------- persistent recurrence kernel ----------------
__device__ __forceinline__ void gbar() {
    __syncthreads();
    if (threadIdx.x == 0) {
        __threadfence();
        unsigned g = g_gen;
        if (atomicAdd(&g_cnt, 1u) == NBLK - 1) {
            g_cnt = 0;
            __threadfence();
            g_gen = g + 1;
        } else {
            while (g_gen == g) __nanosleep(64);
        }
        __threadfence();
    }
    __syncthreads();
}

__device__ __forceinline__ float gatherA_gates(int t, int b, int k)
{
    if (k < EE)        return g_we[(size_t)(t * BB + b) * EE + k];
    if (k < EE + HH)   return __ldcg(&g_weighted[(b << 10) + (k - EE)]);
    if (k < XLEN)      return g_h0[(b << 10) + (k - (EE + HH))];
    return __ldcg(&g_h[(b << 10) + (k - XLEN)]);
}

__global__ __launch_bounds__(256)
void k_recur(const float* __restrict__ attnW, const float* __restrict__ v)
{
    __shared__ float w_s[16][32][4];
    __shared__ float a_s[16][68];
    __shared__ float attn_s[SS];
    __shared__ float red_s[8];

    const int bid = blockIdx.x;
    const int tid = threadIdx.x;
    const int lane = tid & 31;
    const int wid = tid >> 5;
    const int n_l = tid & 31, bq = tid >> 5;
    const int wn = tid >> 3, wk = (tid & 7) * 4;
    const int kk = tid & 31, bb = tid >> 5;

    for (int t = 0; t < TT; t++) {
        // ---- phase A: hW = h @ Wh^T, split-K atomics (blocks 0..127), pipelined ----
        if (bid < 128) {
            int n0 = (bid & 31) * 32;
            int kbeg = (bid >> 5) * 256;
            int kend = kbeg + 256;
            float acc0 = 0.f, acc1 = 0.f;
            const float* Whp = attnW + (size_t)(n0 + wn) * (2 * HH) + wk;
            float4 wv = *(const float4*)(Whp + kbeg);
            float a0 = __ldcg(&g_h[(bb << 10) + kbeg + kk]);
            float a1 = __ldcg(&g_h[((bb + 8) << 10) + kbeg + kk]);
            for (int k0 = kbeg; k0 < kend; k0 += 32) {
                __syncthreads();
                *(float4*)&w_s[wk >> 2][wn][0] = wv;
                a_s[bq][kk] = a0;
                a_s[bq + 8][kk] = a1;
                __syncthreads();
                int kn = k0 + 32;
                if (kn < kend) {
                    wv = *(const float4*)(Whp + kn);
                    a0 = __ldcg(&g_h[(bb << 10) + kn + kk]);
                    a1 = __ldcg(&g_h[((bb + 8) << 10) + kn + kk]);
                }
#pragma unroll
                for (int kg = 0; kg < 8; kg++) {
                    float4 w4 = *(const float4*)&w_s[kg][n_l][0];
                    float4 A0 = *(const float4*)&a_s[bq][kg * 4];
                    float4 A1 = *(const float4*)&a_s[bq + 8][kg * 4];
                    acc0 = fmaf(w4.x, A0.x, acc0); acc0 = fmaf(w4.y, A0.y, acc0);
                    acc0 = fmaf(w4.z, A0.z, acc0); acc0 = fmaf(w4.w, A0.w, acc0);
                    acc1 = fmaf(w4.x, A1.x, acc1); acc1 = fmaf(w4.y, A1.y, acc1);
                    acc1 = fmaf(w4.z, A1.z, acc1); acc1 = fmaf(w4.w, A1.w, acc1);
                }
            }
            atomicAdd(&g_hW[(bq << 10) + n0 + n_l], acc0);
            atomicAdd(&g_hW[((bq + 8) << 10) + n0 + n_l], acc1);
        }
        gbar();

        // ---- phase B: scores (all blocks, warp per (b,s) pair) ----
        for (int p = bid * 8 + wid; p < BB * SS; p += NBLK * 8) {
            int b = p >> 8;
            const float* hsp = g_hsproj + ((size_t)p << 10);
            const float* hw = g_hW + (b << 10);
            float acc = 0.f;
#pragma unroll 8
            for (int i = 0; i < 32; i++) {
                int k = lane + (i << 5);
                acc += v[k] * fast_tanh(__ldcg(&hw[k]) + hsp[k]);
            }
#pragma unroll
            for (int o = 16; o > 0; o >>= 1) acc += __shfl_xor_sync(0xffffffffu, acc, o);
            if (lane == 0) g_score[p] = acc;
        }
        gbar();

        // ---- phase C: softmax + weighted (blocks 0..63) ----
        if (bid < 64) {
            int b = bid >> 2;
            int hbase = (bid & 3) * 256;
            float sc = __ldcg(&g_score[b * SS + tid]);
            float m = sc;
#pragma unroll
            for (int o = 16; o > 0; o >>= 1) m = fmaxf(m, __shfl_xor_sync(0xffffffffu, m, o));
            if (lane == 0) red_s[wid] = m;
            __syncthreads();
            m = red_s[0];
#pragma unroll
            for (int w = 1; w < 8; w++) m = fmaxf(m, red_s[w]);
            float e = __expf(sc - m);
            float sum = e;
#pragma unroll
            for (int o = 16; o > 0; o >>= 1) sum += __shfl_xor_sync(0xffffffffu, sum, o);
            __syncthreads();
            attn_s[tid] = e;
            if (lane == 0) red_s[wid] = sum;
            __syncthreads();
            sum = 0.f;
#pragma unroll
            for (int w = 0; w < 8; w++) sum += red_s[w];
            float inv = __fdividef(1.0f, sum);

            int h = hbase + tid;
            const float* hv = g_hidden + ((size_t)(b * SS) << 10) + h;
            float a0 = 0.f, a1 = 0.f, a2 = 0.f, a3 = 0.f;
            for (int s = 0; s < SS; s += 4) {
                a0 = fmaf(attn_s[s],     hv[(size_t)s << 10],       a0);
                a1 = fmaf(attn_s[s + 1], hv[(size_t)(s + 1) << 10], a1);
                a2 = fmaf(attn_s[s + 2], hv[(size_t)(s + 2) << 10], a2);
                a3 = fmaf(attn_s[s + 3], hv[(size_t)(s + 3) << 10], a3);
            }
            float acc = ((a0 + a1) + (a2 + a3)) * inv;
            g_weighted[(b << 10) + h] = acc;
            g_Z[((size_t)(t * BB + b) << 11) + HH + h] = acc;
        }
        gbar();

        // ---- phase D: gates (blocks 0..127), chunk=64, pipelined ----
        if (bid < 128) {
            int n0 = bid * 32;
            float acc0 = 0.f, acc1 = 0.f;
            const float* Wp = g_Wcat + (size_t)(n0 + wn) * KG + wk;
            float4 wv0 = *(const float4*)(Wp);
            float4 wv1 = *(const float4*)(Wp + 32);
            float a00 = gatherA_gates(t, bb, kk);
            float a01 = gatherA_gates(t, bb, 32 + kk);
            float a10 = gatherA_gates(t, bb + 8, kk);
            float a11 = gatherA_gates(t, bb + 8, 32 + kk);
            for (int k0 = 0; k0 < KG; k0 += 64) {
                __syncthreads();
                *(float4*)&w_s[wk >> 2][wn][0] = wv0;
                *(float4*)&w_s[8 + (wk >> 2)][wn][0] = wv1;
                a_s[bq][kk]          = a00;
                a_s[bq][32 + kk]     = a01;
                a_s[bq + 8][kk]      = a10;
                a_s[bq + 8][32 + kk] = a11;
                __syncthreads();
                int kn = k0 + 64;
                if (kn < KG) {
                    wv0 = *(const float4*)(Wp + kn);
                    wv1 = *(const float4*)(Wp + kn + 32);
                    a00 = gatherA_gates(t, bb, kn + kk);
                    a01 = gatherA_gates(t, bb, kn + 32 + kk);
                    a10 = gatherA_gates(t, bb + 8, kn + kk);
                    a11 = gatherA_gates(t, bb + 8, kn + 32 + kk);
                }
#pragma unroll
                for (int kg = 0; kg < 16; kg++) {
                    float4 w4 = *(const float4*)&w_s[kg][n_l][0];
                    float4 A0 = *(const float4*)&a_s[bq][kg * 4];
                    float4 A1 = *(const float4*)&a_s[bq + 8][kg * 4];
                    acc0 = fmaf(w4.x, A0.x, acc0); acc0 = fmaf(w4.y, A0.y, acc0);
                    acc0 = fmaf(w4.z, A0.z, acc0); acc0 = fmaf(w4.w, A0.w, acc0);
                    acc1 = fmaf(w4.x, A1.x, acc1); acc1 = fmaf(w4.y, A1.y, acc1);
                    acc1 = fmaf(w4.z, A1.z, acc1); acc1 = fmaf(w4.w, A1.w, acc1);
                }
            }
            float bsum = g_bias_sum[n0 + n_l];
            g_gates[bq * G4 + n0 + n_l]       = acc0 + bsum;
            g_gates[(bq + 8) * G4 + n0 + n_l] = acc1 + bsum;
        }
        gbar();

        // ---- phase E: LSTM cell (blocks 0..63) ----
        if (bid < 64) {
            int idx = (bid << 8) + tid;
            int b = idx >> 10, h = idx & 1023;
            const float* g = g_gates + b * G4;
            float ig = __ldcg(&g[h]);
            float fg = __ldcg(&g[HH + h]);
            float gg = __ldcg(&g[2 * HH + h]);
            float og = __ldcg(&g[3 * HH + h]);
            float c = fast_sig(fg) * g_c[idx] + fast_sig(ig) * fast_tanh(gg);
            float hn = fast_sig(og) * fast_tanh(c);
            g_c[idx] = c;
            g_h[idx] = hn;
            g_Z[((size_t)(t * BB + b) << 11) + h] = hn;
            g_hW[idx] = 0.0f;
        }
        gbar();
    }
}

// ---------------- host launch ----------------
extern "C" void kernel_launch(void* const* d_in, const int* in_sizes, int n_in,
                              void* d_out, int out_size)
{
    (void)in_sizes; (void)n_in; (void)out_size;
    const int*   inp    = (const int*)  d_in[0];
    const float* VQ     = (const float*)d_in[1];
    const float* embedW = (const float*)d_in[2];
    const float* transW = (const float*)d_in[3];
    const float* attnW  = (const float*)d_in[4];
    const float* attnb  = (const float*)d_in[5];
    const float* v      = (const float*)d_in[6];
    const float* W_ih   = (const float*)d_in[7];
    const float* W_hh   = (const float*)d_in[8];
    const float* b_ih   = (const float*)d_in[9];
    const float* b_hh   = (const float*)d_in[10];
    const float* predW  = (const float*)d_in[11];
    float* out = (float*)d_out;

    float *p_hidden, *p_hsproj, *p_Z;
    cudaGetSymbolAddress((void**)&p_hidden, g_hidden);
    cudaGetSymbolAddress((void**)&p_hsproj, g_hsproj);
    cudaGetSymbolAddress((void**)&p_Z,      g_Z);

    k_prep<<<2048, 256>>>(inp, embedW, W_ih, W_hh, b_ih, b_hh, out);
    k_biggemm<0><<<dim3(32, 16), 256>>>(VQ, DQD, transW, DQD, 0, nullptr,
                                        p_hidden, HH, BB * SS, DQD);
    k_biggemm<1><<<dim3(32, 16), 256>>>(p_hidden, HH, attnW, 2 * HH, HH, attnb,
                                        p_hsproj, HH, BB * SS, HH);
    k_init_h<<<64, 256>>>();

    // entire 255-step recurrence: ONE kernel, software grid barrier
    k_recur<<<NBLK, 256>>>(attnW, v);

    // hoisted logits GEMM (4080 x 32000, K=2048) in f32x2
    k_logits<<<dim3(32, 250), 256>>>(p_Z, predW, out);
}

// round 14
// speedup vs baseline: 1.3802x; 1.0710x over previous
#include <cuda_runtime.h>

#define BB 16
#define SS 256
#define VV 32000
#define HH 1024
#define EE 512
#define DQD 512
#define TT 255
#define KG 3584
#define G4 4096
#define XLEN 2560
#define NBLK 148

typedef unsigned long long ull;

// ---------------- device scratch ----------------
__device__ __align__(16) float g_hidden[BB*SS*HH];
__device__ __align__(16) float g_hsproj[BB*SS*HH];
__device__ __align__(16) float g_h[BB*HH];
__device__ __align__(16) float g_c[BB*HH];
__device__ __align__(16) float g_hW[BB*HH];
__device__ __align__(16) float g_score[BB*SS];
__device__ __align__(16) float g_Wcat[(size_t)G4*KG];   // rows reordered by colmap
__device__ __align__(16) float g_bias_sum[G4];          // reordered
__device__ __align__(16) float g_we[(size_t)TT*BB*EE];
__device__ __align__(16) float g_Z[(size_t)TT*BB*2*HH];
// x pair table; h segment (k in [2560,3584)) is DOUBLE-BUFFERED:
//   buffer 0 at float offset XLEN*16, buffer 1 at (XLEN+HH)*16. Step t reads buffer t&1.
__device__ __align__(16) float g_xpairf[(KG + HH) * 16];
__device__ unsigned g_cnt = 0;
__device__ volatile unsigned g_gen = 0;

// ---------------- f32x2 helpers ----------------
__device__ __forceinline__ void ffma2(ull& d, ull a, ull b) {
    asm("fma.rn.f32x2 %0, %1, %2, %0;" : "+l"(d) : "l"(a), "l"(b));
}
__device__ __forceinline__ ull dup2(float x) {
    ull r; asm("mov.b64 %0, {%1, %1};" : "=l"(r) : "f"(x)); return r;
}
__device__ __forceinline__ float2 up2(ull u) {
    float2 f; asm("mov.b64 {%0, %1}, %2;" : "=f"(f.x), "=f"(f.y) : "l"(u)); return f;
}

__device__ __forceinline__ float fast_tanh(float x) {
    float e = __expf(2.0f * x);
    return 1.0f - __fdividef(2.0f, e + 1.0f);
}
__device__ __forceinline__ float fast_sig(float x) {
    return __fdividef(1.0f, 1.0f + __expf(-x));
}

// column reorder: block bid owns cols [bid*32, bid*32+32) = gates [i,f,g,o] x h in [bid*8, bid*8+8)
__device__ __forceinline__ int colmap(int c) {
    int g = (c & 31) >> 3, hl = c & 7, blk = c >> 5;
    return g * HH + blk * 8 + hl;
}

// ---------------- prep ----------------
__global__ void k_prep(const int* __restrict__ inp, const float* __restrict__ embedW,
                       const float* __restrict__ W_ih, const float* __restrict__ W_hh,
                       const float* __restrict__ b_ih, const float* __restrict__ b_hh,
                       float* __restrict__ out)
{
    const long long N1 = (long long)G4 * KG;
    const long long N2 = N1 + G4;
    const long long N3 = N2 + (long long)TT * BB * EE;
    const long long N4 = N3 + (long long)BB * VV;
    for (long long i = (long long)blockIdx.x * blockDim.x + threadIdx.x;
         i < N4; i += (long long)gridDim.x * blockDim.x) {
        if (i < N1) {
            int c = (int)(i / KG), k = (int)(i % KG);
            int n = colmap(c);
            g_Wcat[i] = (k < XLEN) ? W_ih[(long long)n * XLEN + k]
                                   : W_hh[(long long)n * HH + (k - XLEN)];
        } else if (i < N2) {
            int c = (int)(i - N1);
            int n = colmap(c);
            g_bias_sum[c] = b_ih[n] + b_hh[n];
        } else if (i < N3) {
            long long j = i - N2;
            int t = (int)(j / (BB * EE));
            int r = (int)(j % (BB * EE));
            int b = r / EE, e = r % EE;
            int tok = inp[b * SS + t];
            g_we[j] = embedW[(long long)tok * EE + e];
        } else {
            long long j = i - N3;
            int b = (int)(j / VV);
            int vv = (int)(j % VV);
            out[(long long)b * SS * VV + vv] = 0.0f;
        }
    }
}

__global__ void k_init_h()
{
    int idx = blockIdx.x * blockDim.x + threadIdx.x;   // 16384
    int b = idx >> 10, h = idx & 1023;
    float c0 = g_hidden[((b * SS + (SS - 1)) << 10) + h];
    g_c[idx] = c0;
    float h0 = tanhf(c0);
    g_h[idx] = h0;
    g_hW[idx] = 0.0f;
    int sl = (b & 7) * 2 + (b >> 3);
    g_xpairf[(EE + HH + h) * 16 + sl] = h0;   // static h0 segment
    g_xpairf[(XLEN + h) * 16 + sl]    = h0;   // h buffer 0: step 0 reads h_0 here
}

// ---------------- big tiled fp32 GEMM (verified; precompute only) ----------------
template<int BIAS_EN>
__global__ __launch_bounds__(256)
void k_biggemm(const float* __restrict__ A, int lda,
               const float* __restrict__ W, int ldw, int woff,
               const float* __restrict__ bias,
               float* __restrict__ C, int ldc, int M, int K)
{
    __shared__ float As[16][132];
    __shared__ float Bs[16][68];
    int tid = threadIdx.x;
    int m0 = blockIdx.x * 128;
    int n0 = blockIdx.y * 64;
    int ar  = tid >> 1;
    int akc = (tid & 1) * 8;
    int wn  = tid >> 2;
    int wkc = (tid & 3) * 4;
    int tx  = tid & 15;
    int ty  = tid >> 4;

    float acc[8][4];
#pragma unroll
    for (int i = 0; i < 8; i++)
#pragma unroll
        for (int j = 0; j < 4; j++) acc[i][j] = 0.0f;

    const float* Arow = A + (size_t)(m0 + ar) * lda;
    const float* Wrow = W + (size_t)(n0 + wn) * ldw + woff;

    for (int k0 = 0; k0 < K; k0 += 16) {
        float4 av0 = *(const float4*)(Arow + k0 + akc);
        float4 av1 = *(const float4*)(Arow + k0 + akc + 4);
        float4 wv  = *(const float4*)(Wrow + k0 + wkc);
        __syncthreads();
        As[akc + 0][ar] = av0.x; As[akc + 1][ar] = av0.y;
        As[akc + 2][ar] = av0.z; As[akc + 3][ar] = av0.w;
        As[akc + 4][ar] = av1.x; As[akc + 5][ar] = av1.y;
        As[akc + 6][ar] = av1.z; As[akc + 7][ar] = av1.w;
        Bs[wkc + 0][wn] = wv.x;  Bs[wkc + 1][wn] = wv.y;
        Bs[wkc + 2][wn] = wv.z;  Bs[wkc + 3][wn] = wv.w;
        __syncthreads();
#pragma unroll
        for (int kk = 0; kk < 16; kk++) {
            float4 a0 = *(const float4*)&As[kk][ty * 8];
            float4 a1 = *(const float4*)&As[kk][ty * 8 + 4];
            float4 bv = *(const float4*)&Bs[kk][tx * 4];
            float ra[8] = {a0.x, a0.y, a0.z, a0.w, a1.x, a1.y, a1.z, a1.w};
            float rb[4] = {bv.x, bv.y, bv.z, bv.w};
#pragma unroll
            for (int i = 0; i < 8; i++)
#pragma unroll
                for (int j = 0; j < 4; j++)
                    acc[i][j] = fmaf(ra[i], rb[j], acc[i][j]);
        }
    }
#pragma unroll
    for (int i = 0; i < 8; i++) {
        int m = m0 + ty * 8 + i;
        float4 r;
        r.x = acc[i][0]; r.y = acc[i][1]; r.z = acc[i][2]; r.w = acc[i][3];
        if (BIAS_EN) {
            int n = n0 + tx * 4;
            r.x += bias[n]; r.y += bias[n + 1]; r.z += bias[n + 2]; r.w += bias[n + 3];
        }
        *(float4*)(C + (size_t)m * ldc + n0 + tx * 4) = r;
    }
}

// ---------------- logits GEMM (verified R9): f32x2, 128x128x16, scatter ----------------
__global__ __launch_bounds__(256)
void k_logits(const float* __restrict__ A, const float* __restrict__ W,
              float* __restrict__ C)
{
    __shared__ float As[16][132];
    __shared__ float Bs[16][132];
    int tid = threadIdx.x;
    int m0 = blockIdx.x * 128;
    int n0 = blockIdx.y * 128;
    int r  = tid >> 1;
    int kc = (tid & 1) * 8;
    int tx = tid & 15;
    int ty = tid >> 4;

    ull acc[8][4];
#pragma unroll
    for (int i = 0; i < 8; i++)
#pragma unroll
        for (int j = 0; j < 4; j++) acc[i][j] = 0ull;

    bool aok = (m0 + r) < (TT * BB);
    const float* Arow = A + (size_t)(m0 + r) * (2 * HH);
    const float* Wrow = W + (size_t)(n0 + r) * (2 * HH);

    float4 av0, av1, bv0, bv1;
    if (aok) {
        av0 = *(const float4*)(Arow + kc);
        av1 = *(const float4*)(Arow + kc + 4);
    } else { av0 = make_float4(0.f,0.f,0.f,0.f); av1 = av0; }
    bv0 = *(const float4*)(Wrow + kc);
    bv1 = *(const float4*)(Wrow + kc + 4);

    for (int k0 = 0; k0 < 2 * HH; k0 += 16) {
        __syncthreads();
        As[kc + 0][r] = av0.x; As[kc + 1][r] = av0.y;
        As[kc + 2][r] = av0.z; As[kc + 3][r] = av0.w;
        As[kc + 4][r] = av1.x; As[kc + 5][r] = av1.y;
        As[kc + 6][r] = av1.z; As[kc + 7][r] = av1.w;
        Bs[kc + 0][r] = bv0.x; Bs[kc + 1][r] = bv0.y;
        Bs[kc + 2][r] = bv0.z; Bs[kc + 3][r] = bv0.w;
        Bs[kc + 4][r] = bv1.x; Bs[kc + 5][r] = bv1.y;
        Bs[kc + 6][r] = bv1.z; Bs[kc + 7][r] = bv1.w;
        __syncthreads();
        int kn = k0 + 16;
        if (kn < 2 * HH) {
            if (aok) {
                av0 = *(const float4*)(Arow + kn + kc);
                av1 = *(const float4*)(Arow + kn + kc + 4);
            }
            bv0 = *(const float4*)(Wrow + kn + kc);
            bv1 = *(const float4*)(Wrow + kn + kc + 4);
        }
#pragma unroll
        for (int kk = 0; kk < 16; kk++) {
            float4 a0 = *(const float4*)&As[kk][ty * 8];
            float4 a1 = *(const float4*)&As[kk][ty * 8 + 4];
            ull b0 = *(const ull*)&Bs[kk][tx * 4];
            ull b1 = *(const ull*)&Bs[kk][tx * 4 + 2];
            ull b2 = *(const ull*)&Bs[kk][64 + tx * 4];
            ull b3 = *(const ull*)&Bs[kk][64 + tx * 4 + 2];
            float aa[8] = {a0.x, a0.y, a0.z, a0.w, a1.x, a1.y, a1.z, a1.w};
#pragma unroll
            for (int i = 0; i < 8; i++) {
                ull ad = dup2(aa[i]);
                ffma2(acc[i][0], ad, b0);
                ffma2(acc[i][1], ad, b1);
                ffma2(acc[i][2], ad, b2);
                ffma2(acc[i][3], ad, b3);
            }
        }
    }
#pragma unroll
    for (int i = 0; i < 8; i++) {
        int m = m0 + ty * 8 + i;
        if (m < TT * BB) {
            int trow = m >> 4, b = m & 15;
            float* dst = C + (size_t)(b * SS + trow + 1) * VV + n0 + tx * 4;
            float2 v0 = up2(acc[i][0]), v1 = up2(acc[i][1]);
            float2 v2 = up2(acc[i][2]), v3 = up2(acc[i][3]);
            float4 w0 = {v0.x, v0.y, v1.x, v1.y};
            float4 w1 = {v2.x, v2.y, v3.x, v3.y};
            *(float4*)dst = w0;
            *(float4*)(dst + 64) = w1;
        }
    }
}

// ---------------- atomic grid barrier (verified R8/R9) ----------------
__device__ __forceinline__ void gbar() {
    __syncthreads();
    if (threadIdx.x == 0) {
        __threadfence();
        unsigned g = g_gen;
        if (atomicAdd(&g_cnt, 1u) == NBLK - 1) {
            g_cnt = 0;
            __threadfence();
            g_gen = g + 1;
        } else {
            while (g_gen == g) __nanosleep(64);
        }
        __threadfence();
    }
    __syncthreads();
}

// ---------------- persistent recurrence ----------------
__global__ __launch_bounds__(256)
void k_recur(const float* __restrict__ attnW, const float* __restrict__ v)
{
    __shared__ __align__(16) float w_s[32][68];      // gates W tile [n][k]
    __shared__ __align__(16) ull  x2_s[8][66];       // x pairs [pair][k]
    __shared__ float gsm[32][16];                    // gate values [c_local][b]
    __shared__ float aw_s[8][32][4];                 // phase A W
    __shared__ float aa_s[16][36];                   // phase A x
    __shared__ float attn_s[SS];
    __shared__ float red_s[8];

    const int bid = blockIdx.x;
    const int tid = threadIdx.x;
    const int lane = tid & 31;
    const int wid = tid >> 5;
    // phase A ids
    const int n_l = tid & 31, bq = tid >> 5;
    const int wn = tid >> 3, wk = (tid & 7) * 4;
    const int kk = tid & 31, bb = tid >> 5;
    // phase D compute ids: warp = 8 n-cols x 4 pairs
    const int nl = (wid & 3) * 8 + (lane >> 2);
    const int pr = (wid >> 2) * 4 + (lane & 3);
    // phase D staging ids
    const int sn = tid >> 3;
    const int sk = (tid & 7) * 8;
    const int xk = tid >> 2;
    const int xp = (tid & 3) * 2;

    // persistent cell state (block bid owns h in [bid*8, bid*8+8))
    float creg = 0.0f;
    if (bid < 128 && tid < 128)
        creg = g_c[((tid & 15) << 10) + bid * 8 + (tid >> 4)];

    const float* Wp = g_Wcat + (size_t)(bid * 32 + sn) * KG + sk;   // valid for bid<128
    const float* Xb = g_xpairf + tid * 4;

    for (int t = 0; t < TT; t++) {
        // h buffer select: step t reads h from buffer (t&1); cell writes buffer ((t+1)&1)
        const int hof = (t & 1) << 14;               // 16384 floats = HH*16

        // ===== phase A: hW = h @ Wh^T split-K atomics (bid<128); we->xpair copy (bid>=128) ====
        if (bid < 128) {
            int an0 = (bid & 31) * 32;
            int kbeg = (bid >> 5) * 256;
            int kend = kbeg + 256;
            float acc0 = 0.f, acc1 = 0.f;
            const float* Whp = attnW + (size_t)(an0 + wn) * (2 * HH) + wk;
            float4 wv = *(const float4*)(Whp + kbeg);
            float a0 = __ldcg(&g_h[(bb << 10) + kbeg + kk]);
            float a1 = __ldcg(&g_h[((bb + 8) << 10) + kbeg + kk]);
            for (int k0 = kbeg; k0 < kend; k0 += 32) {
                __syncthreads();
                *(float4*)&aw_s[wk >> 2][wn][0] = wv;
                aa_s[bq][kk] = a0;
                aa_s[bq + 8][kk] = a1;
                __syncthreads();
                int kn = k0 + 32;
                if (kn < kend) {
                    wv = *(const float4*)(Whp + kn);
                    a0 = __ldcg(&g_h[(bb << 10) + kn + kk]);
                    a1 = __ldcg(&g_h[((bb + 8) << 10) + kn + kk]);
                }
#pragma unroll
                for (int kg = 0; kg < 8; kg++) {
                    float4 w4 = *(const float4*)&aw_s[kg][n_l][0];
                    float4 A0 = *(const float4*)&aa_s[bq][kg * 4];
                    float4 A1 = *(const float4*)&aa_s[bq + 8][kg * 4];
                    acc0 = fmaf(w4.x, A0.x, acc0); acc0 = fmaf(w4.y, A0.y, acc0);
                    acc0 = fmaf(w4.z, A0.z, acc0); acc0 = fmaf(w4.w, A0.w, acc0);
                    acc1 = fmaf(w4.x, A1.x, acc1); acc1 = fmaf(w4.y, A1.y, acc1);
                    acc1 = fmaf(w4.z, A1.z, acc1); acc1 = fmaf(w4.w, A1.w, acc1);
                }
            }
            atomicAdd(&g_hW[(bq << 10) + an0 + n_l], acc0);
            atomicAdd(&g_hW[((bq + 8) << 10) + an0 + n_l], acc1);
        } else {
            for (int j = (bid - 128) * 256 + tid; j < BB * EE; j += 20 * 256) {
                int k = j >> 4, b = j & 15;
                g_xpairf[k * 16 + (b & 7) * 2 + (b >> 3)] =
                    g_we[((size_t)t * BB + b) * EE + k];
            }
        }
        gbar();

        // ===== phase B: scores (all blocks, warp per (b,s)) =====
        for (int p = bid * 8 + wid; p < BB * SS; p += NBLK * 8) {
            int b = p >> 8;
            const float* hsp = g_hsproj + ((size_t)p << 10);
            const float* hw = g_hW + (b << 10);
            float acc = 0.f;
#pragma unroll 8
            for (int i = 0; i < 32; i++) {
                int k = lane + (i << 5);
                acc += v[k] * fast_tanh(__ldcg(&hw[k]) + hsp[k]);
            }
#pragma unroll
            for (int o = 16; o > 0; o >>= 1) acc += __shfl_xor_sync(0xffffffffu, acc, o);
            if (lane == 0) g_score[p] = acc;
        }
        gbar();

        // ===== phase C: softmax + weighted (bid<64) -> xpair + Z =====
        if (bid < 64) {
            int b = bid >> 2;
            int hbase = (bid & 3) * 256;
            float sc = __ldcg(&g_score[b * SS + tid]);
            float m = sc;
#pragma unroll
            for (int o = 16; o > 0; o >>= 1) m = fmaxf(m, __shfl_xor_sync(0xffffffffu, m, o));
            if (lane == 0) red_s[wid] = m;
            __syncthreads();
            m = red_s[0];
#pragma unroll
            for (int w = 1; w < 8; w++) m = fmaxf(m, red_s[w]);
            float e = __expf(sc - m);
            float sum = e;
#pragma unroll
            for (int o = 16; o > 0; o >>= 1) sum += __shfl_xor_sync(0xffffffffu, sum, o);
            __syncthreads();
            attn_s[tid] = e;
            if (lane == 0) red_s[wid] = sum;
            __syncthreads();
            sum = 0.f;
#pragma unroll
            for (int w = 0; w < 8; w++) sum += red_s[w];
            float inv = __fdividef(1.0f, sum);

            int h = hbase + tid;
            const float* hv = g_hidden + ((size_t)(b * SS) << 10) + h;
            float a0 = 0.f, a1 = 0.f, a2 = 0.f, a3 = 0.f;
            for (int s = 0; s < SS; s += 4) {
                a0 = fmaf(attn_s[s],     hv[(size_t)s << 10],       a0);
                a1 = fmaf(attn_s[s + 1], hv[(size_t)(s + 1) << 10], a1);
                a2 = fmaf(attn_s[s + 2], hv[(size_t)(s + 2) << 10], a2);
                a3 = fmaf(attn_s[s + 3], hv[(size_t)(s + 3) << 10], a3);
            }
            float acc = ((a0 + a1) + (a2 + a3)) * inv;
            g_xpairf[(EE + h) * 16 + (b & 7) * 2 + (b >> 3)] = acc;
            g_Z[((size_t)(t * BB + b) << 11) + HH + h] = acc;
        }
        // prefetch first 2 W chunks for phase D before the barrier (Wcat immutable)
        float4 wa0, wb0, wa1, wb1;
        if (bid < 128) {
            wa0 = *(const float4*)(Wp);
            wb0 = *(const float4*)(Wp + 4);
            wa1 = *(const float4*)(Wp + 64);
            wb1 = *(const float4*)(Wp + 68);
        }
        gbar();

        // ===== phase D+E: gates (f32x2) + fused LSTM cell (bid<128) =====
        if (bid < 128) {
            ulonglong2 xv0 = __ldcg((const ulonglong2*)(Xb));
            ulonglong2 xv1 = __ldcg((const ulonglong2*)(Xb + 1024));
            ull acA = 0ull, acB = 0ull;
            for (int c = 0; c < 56; c += 2) {
                // even chunk
                __syncthreads();
                *(float4*)&w_s[sn][sk] = wa0;
                *(float4*)&w_s[sn][sk + 4] = wb0;
                x2_s[xp][xk] = xv0.x;
                x2_s[xp + 1][xk] = xv0.y;
                __syncthreads();
                {
                    int cn = (c + 2 < 56) ? c + 2 : 54;
                    wa0 = *(const float4*)(Wp + cn * 64);
                    wb0 = *(const float4*)(Wp + cn * 64 + 4);
                    xv0 = __ldcg((const ulonglong2*)(Xb + cn * 1024 + (cn >= 40 ? hof : 0)));
                }
#pragma unroll
                for (int kg = 0; kg < 16; kg++) {
                    float4 w = *(const float4*)&w_s[nl][kg * 4];
                    ulonglong2 xa = *(const ulonglong2*)&x2_s[pr][kg * 4];
                    ulonglong2 xc = *(const ulonglong2*)&x2_s[pr][kg * 4 + 2];
                    ffma2(acA, dup2(w.x), xa.x);
                    ffma2(acB, dup2(w.y), xa.y);
                    ffma2(acA, dup2(w.z), xc.x);
                    ffma2(acB, dup2(w.w), xc.y);
                }
                // odd chunk
                __syncthreads();
                *(float4*)&w_s[sn][sk] = wa1;
                *(float4*)&w_s[sn][sk + 4] = wb1;
                x2_s[xp][xk] = xv1.x;
                x2_s[xp + 1][xk] = xv1.y;
                __syncthreads();
                {
                    int cn = (c + 3 < 56) ? c + 3 : 55;
                    wa1 = *(const float4*)(Wp + cn * 64);
                    wb1 = *(const float4*)(Wp + cn * 64 + 4);
                    xv1 = __ldcg((const ulonglong2*)(Xb + cn * 1024 + (cn >= 40 ? hof : 0)));
                }
#pragma unroll
                for (int kg = 0; kg < 16; kg++) {
                    float4 w = *(const float4*)&w_s[nl][kg * 4];
                    ulonglong2 xa = *(const ulonglong2*)&x2_s[pr][kg * 4];
                    ulonglong2 xc = *(const ulonglong2*)&x2_s[pr][kg * 4 + 2];
                    ffma2(acA, dup2(w.x), xa.x);
                    ffma2(acB, dup2(w.y), xa.y);
                    ffma2(acA, dup2(w.z), xc.x);
                    ffma2(acB, dup2(w.w), xc.y);
                }
            }
            {
                float2 ga = up2(acA), gb = up2(acB);
                float bsum = g_bias_sum[bid * 32 + nl];
                gsm[nl][pr]     = ga.x + gb.x + bsum;
                gsm[nl][pr + 8] = ga.y + gb.y + bsum;
            }
            __syncthreads();
            if (tid < 128) {
                int b = tid & 15, hl = tid >> 4;
                float ig = gsm[hl][b];
                float fg = gsm[8 + hl][b];
                float gg = gsm[16 + hl][b];
                float og = gsm[24 + hl][b];
                float cn = fast_sig(fg) * creg + fast_sig(ig) * fast_tanh(gg);
                float hn = fast_sig(og) * fast_tanh(cn);
                creg = cn;
                int hg = bid * 8 + hl;
                int idx = (b << 10) + hg;
                g_h[idx] = hn;
                // write h_{t+1} into the OTHER h buffer (no race with step-t readers)
                g_xpairf[(XLEN + (((t + 1) & 1) << 10) + hg) * 16 + (b & 7) * 2 + (b >> 3)] = hn;
                g_Z[((size_t)(t * BB + b) << 11) + hg] = hn;
                g_hW[idx] = 0.0f;
            }
        }
        gbar();
    }
}

// ---------------- host launch ----------------
extern "C" void kernel_launch(void* const* d_in, const int* in_sizes, int n_in,
                              void* d_out, int out_size)
{
    (void)in_sizes; (void)n_in; (void)out_size;
    const int*   inp    = (const int*)  d_in[0];
    const float* VQ     = (const float*)d_in[1];
    const float* embedW = (const float*)d_in[2];
    const float* transW = (const float*)d_in[3];
    const float* attnW  = (const float*)d_in[4];
    const float* attnb  = (const float*)d_in[5];
    const float* v      = (const float*)d_in[6];
    const float* W_ih   = (const float*)d_in[7];
    const float* W_hh   = (const float*)d_in[8];
    const float* b_ih   = (const float*)d_in[9];
    const float* b_hh   = (const float*)d_in[10];
    const float* predW  = (const float*)d_in[11];
    float* out = (float*)d_out;

    float *p_hidden, *p_hsproj, *p_Z;
    cudaGetSymbolAddress((void**)&p_hidden, g_hidden);
    cudaGetSymbolAddress((void**)&p_hsproj, g_hsproj);
    cudaGetSymbolAddress((void**)&p_Z,      g_Z);

    k_prep<<<2048, 256>>>(inp, embedW, W_ih, W_hh, b_ih, b_hh, out);
    k_biggemm<0><<<dim3(32, 16), 256>>>(VQ, DQD, transW, DQD, 0, nullptr,
                                        p_hidden, HH, BB * SS, DQD);
    k_biggemm<1><<<dim3(32, 16), 256>>>(p_hidden, HH, attnW, 2 * HH, HH, attnb,
                                        p_hsproj, HH, BB * SS, HH);
    k_init_h<<<64, 256>>>();

    // entire 255-step recurrence: ONE kernel, atomic grid barrier (verified)
    k_recur<<<NBLK, 256>>>(attnW, v);

    // hoisted logits GEMM (4080 x 32000, K=2048) in f32x2
    k_logits<<<dim3(32, 250), 256>>>(p_Z, predW, out);
}

// round 16
// speedup vs baseline: 1.5467x; 1.1207x over previous
#include <cuda_runtime.h>
#include <cuda_bf16.h>

#define BB 16
#define SS 256
#define VV 32000
#define HH 1024
#define EE 512
#define DQD 512
#define TT 255
#define KG 3584
#define G4 4096
#define XLEN 2560
#define NBLK 148

typedef unsigned long long ull;

// ---------------- device scratch ----------------
__device__ __align__(16) float g_hidden[BB*SS*HH];
__device__ __align__(16) float g_hsproj[BB*SS*HH];
__device__ __align__(16) float g_h[BB*HH];
__device__ __align__(16) float g_c[BB*HH];
__device__ __align__(16) float g_hW[BB*HH];
__device__ __align__(16) float g_score[BB*SS];
__device__ __align__(16) float g_Wcat[(size_t)G4*KG];   // rows reordered by colmap
__device__ __align__(16) float g_bias_sum[G4];          // reordered
__device__ __align__(16) float g_we[(size_t)TT*BB*EE];
__device__ __align__(16) float g_Z[(size_t)TT*BB*2*HH];
// x pair table; h segment (k in [2560,3584)) double-buffered
__device__ __align__(16) float g_xpairf[(KG + HH) * 16];
__device__ unsigned g_cnt = 0;
__device__ volatile unsigned g_gen = 0;

// bf16 split operands for the tensor-core logits GEMM
__device__ __align__(16) __nv_bfloat16 g_Bhi[(size_t)VV*2*HH];
__device__ __align__(16) __nv_bfloat16 g_Blo[(size_t)VV*2*HH];
__device__ __align__(16) __nv_bfloat16 g_Zhi[(size_t)4096*2*HH];   // padded rows
__device__ __align__(16) __nv_bfloat16 g_Zlo[(size_t)4096*2*HH];

// ---------------- f32x2 helpers ----------------
__device__ __forceinline__ void ffma2(ull& d, ull a, ull b) {
    asm("fma.rn.f32x2 %0, %1, %2, %0;" : "+l"(d) : "l"(a), "l"(b));
}
__device__ __forceinline__ ull dup2(float x) {
    ull r; asm("mov.b64 %0, {%1, %1};" : "=l"(r) : "f"(x)); return r;
}
__device__ __forceinline__ float2 up2(ull u) {
    float2 f; asm("mov.b64 {%0, %1}, %2;" : "=f"(f.x), "=f"(f.y) : "l"(u)); return f;
}

__device__ __forceinline__ float fast_tanh(float x) {
    float e = __expf(2.0f * x);
    return 1.0f - __fdividef(2.0f, e + 1.0f);
}
__device__ __forceinline__ float fast_sig(float x) {
    return __fdividef(1.0f, 1.0f + __expf(-x));
}

__device__ __forceinline__ unsigned smem_u32(const void* p) {
    unsigned a;
    asm("{ .reg .u64 t; cvta.to.shared.u64 t, %1; cvt.u32.u64 %0, t; }" : "=r"(a) : "l"(p));
    return a;
}

// ---------------- mma.sync helpers (sm_80+ PTX, compiles for compute_103) ----------------
#define LDSM4(r, a)                                                                   \
    asm volatile("ldmatrix.sync.aligned.m8n8.x4.shared.b16 {%0,%1,%2,%3}, [%4];"      \
        : "=r"((r)[0]), "=r"((r)[1]), "=r"((r)[2]), "=r"((r)[3]) : "r"(a))
#define LDSM2(r, a)                                                                   \
    asm volatile("ldmatrix.sync.aligned.m8n8.x2.shared.b16 {%0,%1}, [%2];"            \
        : "=r"((r)[0]), "=r"((r)[1]) : "r"(a))
#define MMA_BF16(d, a, b)                                                             \
    asm volatile("mma.sync.aligned.m16n8k16.row.col.f32.bf16.bf16.f32 "               \
        "{%0,%1,%2,%3}, {%4,%5,%6,%7}, {%8,%9}, {%0,%1,%2,%3};"                       \
        : "+f"((d)[0]), "+f"((d)[1]), "+f"((d)[2]), "+f"((d)[3])                      \
        : "r"((a)[0]), "r"((a)[1]), "r"((a)[2]), "r"((a)[3]), "r"((b)[0]), "r"((b)[1]))

// column reorder: block bid owns cols [bid*32, bid*32+32) = gates [i,f,g,o] x h in [bid*8, bid*8+8)
__device__ __forceinline__ int colmap(int c) {
    int g = (c & 31) >> 3, hl = c & 7, blk = c >> 5;
    return g * HH + blk * 8 + hl;
}

// ---------------- prep ----------------
__global__ void k_prep(const int* __restrict__ inp, const float* __restrict__ embedW,
                       const float* __restrict__ W_ih, const float* __restrict__ W_hh,
                       const float* __restrict__ b_ih, const float* __restrict__ b_hh,
                       float* __restrict__ out)
{
    const long long N1 = (long long)G4 * KG;
    const long long N2 = N1 + G4;
    const long long N3 = N2 + (long long)TT * BB * EE;
    const long long N4 = N3 + (long long)BB * VV;
    for (long long i = (long long)blockIdx.x * blockDim.x + threadIdx.x;
         i < N4; i += (long long)gridDim.x * blockDim.x) {
        if (i < N1) {
            int c = (int)(i / KG), k = (int)(i % KG);
            int n = colmap(c);
            g_Wcat[i] = (k < XLEN) ? W_ih[(long long)n * XLEN + k]
                                   : W_hh[(long long)n * HH + (k - XLEN)];
        } else if (i < N2) {
            int c = (int)(i - N1);
            int n = colmap(c);
            g_bias_sum[c] = b_ih[n] + b_hh[n];
        } else if (i < N3) {
            long long j = i - N2;
            int t = (int)(j / (BB * EE));
            int r = (int)(j % (BB * EE));
            int b = r / EE, e = r % EE;
            int tok = inp[b * SS + t];
            g_we[j] = embedW[(long long)tok * EE + e];
        } else {
            long long j = i - N3;
            int b = (int)(j / VV);
            int vv = (int)(j % VV);
            out[(long long)b * SS * VV + vv] = 0.0f;
        }
    }
}

__global__ void k_init_h()
{
    int idx = blockIdx.x * blockDim.x + threadIdx.x;   // 16384
    int b = idx >> 10, h = idx & 1023;
    float c0 = g_hidden[((b * SS + (SS - 1)) << 10) + h];
    g_c[idx] = c0;
    float h0 = tanhf(c0);
    g_h[idx] = h0;
    g_hW[idx] = 0.0f;
    int sl = (b & 7) * 2 + (b >> 3);
    g_xpairf[(EE + HH + h) * 16 + sl] = h0;   // static h0 segment
    g_xpairf[(XLEN + h) * 16 + sl]    = h0;   // h buffer 0: step 0 reads h_0 here
}

// ---------------- fp32 -> bf16 hi/lo split ----------------
__global__ void k_cvt(const float* __restrict__ src, __nv_bfloat16* __restrict__ hi,
                      __nv_bfloat16* __restrict__ lo, size_t n_src, size_t n_tot)
{
    for (size_t i = (size_t)blockIdx.x * blockDim.x + threadIdx.x; i < n_tot;
         i += (size_t)gridDim.x * blockDim.x) {
        float x = (i < n_src) ? src[i] : 0.0f;
        __nv_bfloat16 h = __float2bfloat16(x);
        hi[i] = h;
        lo[i] = __float2bfloat16(x - __bfloat162float(h));
    }
}

// ---------------- big tiled fp32 GEMM (verified; precompute only) ----------------
template<int BIAS_EN>
__global__ __launch_bounds__(256)
void k_biggemm(const float* __restrict__ A, int lda,
               const float* __restrict__ W, int ldw, int woff,
               const float* __restrict__ bias,
               float* __restrict__ C, int ldc, int M, int K)
{
    __shared__ float As[16][132];
    __shared__ float Bs[16][68];
    int tid = threadIdx.x;
    int m0 = blockIdx.x * 128;
    int n0 = blockIdx.y * 64;
    int ar  = tid >> 1;
    int akc = (tid & 1) * 8;
    int wn  = tid >> 2;
    int wkc = (tid & 3) * 4;
    int tx  = tid & 15;
    int ty  = tid >> 4;

    float acc[8][4];
#pragma unroll
    for (int i = 0; i < 8; i++)
#pragma unroll
        for (int j = 0; j < 4; j++) acc[i][j] = 0.0f;

    const float* Arow = A + (size_t)(m0 + ar) * lda;
    const float* Wrow = W + (size_t)(n0 + wn) * ldw + woff;

    for (int k0 = 0; k0 < K; k0 += 16) {
        float4 av0 = *(const float4*)(Arow + k0 + akc);
        float4 av1 = *(const float4*)(Arow + k0 + akc + 4);
        float4 wv  = *(const float4*)(Wrow + k0 + wkc);
        __syncthreads();
        As[akc + 0][ar] = av0.x; As[akc + 1][ar] = av0.y;
        As[akc + 2][ar] = av0.z; As[akc + 3][ar] = av0.w;
        As[akc + 4][ar] = av1.x; As[akc + 5][ar] = av1.y;
        As[akc + 6][ar] = av1.z; As[akc + 7][ar] = av1.w;
        Bs[wkc + 0][wn] = wv.x;  Bs[wkc + 1][wn] = wv.y;
        Bs[wkc + 2][wn] = wv.z;  Bs[wkc + 3][wn] = wv.w;
        __syncthreads();
#pragma unroll
        for (int kk = 0; kk < 16; kk++) {
            float4 a0 = *(const float4*)&As[kk][ty * 8];
            float4 a1 = *(const float4*)&As[kk][ty * 8 + 4];
            float4 bv = *(const float4*)&Bs[kk][tx * 4];
            float ra[8] = {a0.x, a0.y, a0.z, a0.w, a1.x, a1.y, a1.z, a1.w};
            float rb[4] = {bv.x, bv.y, bv.z, bv.w};
#pragma unroll
            for (int i = 0; i < 8; i++)
#pragma unroll
                for (int j = 0; j < 4; j++)
                    acc[i][j] = fmaf(ra[i], rb[j], acc[i][j]);
        }
    }
#pragma unroll
    for (int i = 0; i < 8; i++) {
        int m = m0 + ty * 8 + i;
        float4 r;
        r.x = acc[i][0]; r.y = acc[i][1]; r.z = acc[i][2]; r.w = acc[i][3];
        if (BIAS_EN) {
            int n = n0 + tx * 4;
            r.x += bias[n]; r.y += bias[n + 1]; r.z += bias[n + 2]; r.w += bias[n + 3];
        }
        *(float4*)(C + (size_t)m * ldc + n0 + tx * 4) = r;
    }
}

// ---------------- tensor-core logits GEMM: mma.sync bf16 3-term split ----------------
// D[m][n] = sum_k Z[m][k]*predW[n][k];  out row = b*SS + t + 1, m = t*16 + b
// 128x128 tile, 8 warps (2m x 4n), warp tile 64x32, BK=32, double-buffered smem.
#define LDS_STRIDE 80            // bytes per smem row: 32 bf16 data + 8 pad
#define TILE_B (128 * LDS_STRIDE)        // 10240
#define STAGE_B (4 * TILE_B)             // 40960: [Ahi|Alo|Bhi|Blo]
#define MMA_SMEM (2 * STAGE_B)           // 81920

__global__ __launch_bounds__(256)
void k_logits_mma(const __nv_bfloat16* __restrict__ Ahi, const __nv_bfloat16* __restrict__ Alo,
                  const __nv_bfloat16* __restrict__ Bhi, const __nv_bfloat16* __restrict__ Blo,
                  float* __restrict__ C)
{
    extern __shared__ char sm[];
    const unsigned sb = smem_u32(sm);
    const int tid = threadIdx.x, lane = tid & 31, wid = tid >> 5;
    const int wm = wid & 1, wn = wid >> 1;     // 2m x 4n warp grid
    const int m0 = blockIdx.x * 128;
    const int n0 = blockIdx.y * 128;

    const __nv_bfloat16* gsrc[4] = {
        Ahi + (size_t)m0 * 2048, Alo + (size_t)m0 * 2048,
        Bhi + (size_t)n0 * 2048, Blo + (size_t)n0 * 2048 };

    float acc[4][4][4];
#pragma unroll
    for (int i = 0; i < 4; i++)
#pragma unroll
        for (int j = 0; j < 4; j++)
#pragma unroll
            for (int q = 0; q < 4; q++) acc[i][j][q] = 0.0f;

    const int r0 = tid >> 2,  s0 = tid & 3;            // staging coords (i=0)
    const int r1 = (256 + tid) >> 2, s1 = tid & 3;     // i=1

    float4 v[8];
    auto ldchunk = [&](int c) {
#pragma unroll
        for (int t = 0; t < 4; t++) {
            const __nv_bfloat16* g = gsrc[t] + (size_t)c * 32;
            v[t * 2 + 0] = *(const float4*)(g + (size_t)r0 * 2048 + s0 * 8);
            v[t * 2 + 1] = *(const float4*)(g + (size_t)r1 * 2048 + s1 * 8);
        }
    };
    auto stchunk = [&](int buf) {
        char* base = sm + buf * STAGE_B;
#pragma unroll
        for (int t = 0; t < 4; t++) {
            *(float4*)(base + t * TILE_B + r0 * LDS_STRIDE + s0 * 16) = v[t * 2 + 0];
            *(float4*)(base + t * TILE_B + r1 * LDS_STRIDE + s1 * 16) = v[t * 2 + 1];
        }
    };

    ldchunk(0);
    stchunk(0);
    __syncthreads();

    for (int c = 0; c < 64; c++) {
        if (c < 63) ldchunk(c + 1);
        const unsigned sbase = sb + (c & 1) * STAGE_B;
#pragma unroll
        for (int kf = 0; kf < 2; kf++) {
            unsigned ah[4][4], al[4][4], bh[4][2], bl[4][2];
#pragma unroll
            for (int mf = 0; mf < 4; mf++) {
                unsigned ra = (unsigned)((wm * 64 + mf * 16 + (lane & 15)) * LDS_STRIDE
                                         + kf * 32 + ((lane >> 4) & 1) * 16);
                LDSM4(ah[mf], sbase + 0 * TILE_B + ra);
                LDSM4(al[mf], sbase + 1 * TILE_B + ra);
            }
#pragma unroll
            for (int nf = 0; nf < 4; nf++) {
                unsigned rb = (unsigned)((wn * 32 + nf * 8 + (lane & 7)) * LDS_STRIDE
                                         + kf * 32 + ((lane >> 3) & 1) * 16);
                LDSM2(bh[nf], sbase + 2 * TILE_B + rb);
                LDSM2(bl[nf], sbase + 3 * TILE_B + rb);
            }
#pragma unroll
            for (int mf = 0; mf < 4; mf++)
#pragma unroll
                for (int nf = 0; nf < 4; nf++) {
                    MMA_BF16(acc[mf][nf], ah[mf], bh[nf]);
                    MMA_BF16(acc[mf][nf], al[mf], bh[nf]);
                    MMA_BF16(acc[mf][nf], ah[mf], bl[nf]);
                }
        }
        if (c < 63) {
            __syncthreads();
            stchunk((c + 1) & 1);
            __syncthreads();
        }
    }

    // epilogue: scatter fp32 results (m -> out row b*SS + t + 1)
#pragma unroll
    for (int mf = 0; mf < 4; mf++)
#pragma unroll
        for (int i = 0; i < 2; i++) {
            int m = m0 + wm * 64 + mf * 16 + (lane >> 2) + i * 8;
            if (m < TT * BB) {
                int trow = m >> 4, b = m & 15;
                float* dst = C + (size_t)(b * SS + trow + 1) * VV
                             + n0 + wn * 32 + (lane & 3) * 2;
#pragma unroll
                for (int nf = 0; nf < 4; nf++) {
                    float2 w;
                    w.x = acc[mf][nf][i * 2 + 0];
                    w.y = acc[mf][nf][i * 2 + 1];
                    *(float2*)(dst + nf * 8) = w;
                }
            }
        }
}

// ---------------- atomic grid barrier (verified) ----------------
__device__ __forceinline__ void gbar() {
    __syncthreads();
    if (threadIdx.x == 0) {
        __threadfence();
        unsigned g = g_gen;
        if (atomicAdd(&g_cnt, 1u) == NBLK - 1) {
            g_cnt = 0;
            __threadfence();
            g_gen = g + 1;
        } else {
            while (g_gen == g) __nanosleep(64);
        }
        __threadfence();
    }
    __syncthreads();
}

// ---------------- persistent recurrence (verified R13) ----------------
__global__ __launch_bounds__(256)
void k_recur(const float* __restrict__ attnW, const float* __restrict__ v)
{
    __shared__ __align__(16) float w_s[32][68];
    __shared__ __align__(16) ull  x2_s[8][66];
    __shared__ float gsm[32][16];
    __shared__ float aw_s[8][32][4];
    __shared__ float aa_s[16][36];
    __shared__ float attn_s[SS];
    __shared__ float red_s[8];

    const int bid = blockIdx.x;
    const int tid = threadIdx.x;
    const int lane = tid & 31;
    const int wid = tid >> 5;
    const int n_l = tid & 31, bq = tid >> 5;
    const int wn = tid >> 3, wk = (tid & 7) * 4;
    const int kk = tid & 31, bb = tid >> 5;
    const int nl = (wid & 3) * 8 + (lane >> 2);
    const int pr = (wid >> 2) * 4 + (lane & 3);
    const int sn = tid >> 3;
    const int sk = (tid & 7) * 8;
    const int xk = tid >> 2;
    const int xp = (tid & 3) * 2;

    float creg = 0.0f;
    if (bid < 128 && tid < 128)
        creg = g_c[((tid & 15) << 10) + bid * 8 + (tid >> 4)];

    const float* Wp = g_Wcat + (size_t)(bid * 32 + sn) * KG + sk;
    const float* Xb = g_xpairf + tid * 4;

    for (int t = 0; t < TT; t++) {
        const int hof = (t & 1) << 14;

        if (bid < 128) {
            int an0 = (bid & 31) * 32;
            int kbeg = (bid >> 5) * 256;
            int kend = kbeg + 256;
            float acc0 = 0.f, acc1 = 0.f;
            const float* Whp = attnW + (size_t)(an0 + wn) * (2 * HH) + wk;
            float4 wv = *(const float4*)(Whp + kbeg);
            float a0 = __ldcg(&g_h[(bb << 10) + kbeg + kk]);
            float a1 = __ldcg(&g_h[((bb + 8) << 10) + kbeg + kk]);
            for (int k0 = kbeg; k0 < kend; k0 += 32) {
                __syncthreads();
                *(float4*)&aw_s[wk >> 2][wn][0] = wv;
                aa_s[bq][kk] = a0;
                aa_s[bq + 8][kk] = a1;
                __syncthreads();
                int kn = k0 + 32;
                if (kn < kend) {
                    wv = *(const float4*)(Whp + kn);
                    a0 = __ldcg(&g_h[(bb << 10) + kn + kk]);
                    a1 = __ldcg(&g_h[((bb + 8) << 10) + kn + kk]);
                }
#pragma unroll
                for (int kg = 0; kg < 8; kg++) {
                    float4 w4 = *(const float4*)&aw_s[kg][n_l][0];
                    float4 A0 = *(const float4*)&aa_s[bq][kg * 4];
                    float4 A1 = *(const float4*)&aa_s[bq + 8][kg * 4];
                    acc0 = fmaf(w4.x, A0.x, acc0); acc0 = fmaf(w4.y, A0.y, acc0);
                    acc0 = fmaf(w4.z, A0.z, acc0); acc0 = fmaf(w4.w, A0.w, acc0);
                    acc1 = fmaf(w4.x, A1.x, acc1); acc1 = fmaf(w4.y, A1.y, acc1);
                    acc1 = fmaf(w4.z, A1.z, acc1); acc1 = fmaf(w4.w, A1.w, acc1);
                }
            }
            atomicAdd(&g_hW[(bq << 10) + an0 + n_l], acc0);
            atomicAdd(&g_hW[((bq + 8) << 10) + an0 + n_l], acc1);
        } else {
            for (int j = (bid - 128) * 256 + tid; j < BB * EE; j += 20 * 256) {
                int k = j >> 4, b = j & 15;
                g_xpairf[k * 16 + (b & 7) * 2 + (b >> 3)] =
                    g_we[((size_t)t * BB + b) * EE + k];
            }
        }
        gbar();

        for (int p = bid * 8 + wid; p < BB * SS; p += NBLK * 8) {
            int b = p >> 8;
            const float* hsp = g_hsproj + ((size_t)p << 10);
            const float* hw = g_hW + (b << 10);
            float acc = 0.f;
#pragma unroll 8
            for (int i = 0; i < 32; i++) {
                int k = lane + (i << 5);
                acc += v[k] * fast_tanh(__ldcg(&hw[k]) + hsp[k]);
            }
#pragma unroll
            for (int o = 16; o > 0; o >>= 1) acc += __shfl_xor_sync(0xffffffffu, acc, o);
            if (lane == 0) g_score[p] = acc;
        }
        gbar();

        if (bid < 64) {
            int b = bid >> 2;
            int hbase = (bid & 3) * 256;
            float sc = __ldcg(&g_score[b * SS + tid]);
            float m = sc;
#pragma unroll
            for (int o = 16; o > 0; o >>= 1) m = fmaxf(m, __shfl_xor_sync(0xffffffffu, m, o));
            if (lane == 0) red_s[wid] = m;
            __syncthreads();
            m = red_s[0];
#pragma unroll
            for (int w = 1; w < 8; w++) m = fmaxf(m, red_s[w]);
            float e = __expf(sc - m);
            float sum = e;
#pragma unroll
            for (int o = 16; o > 0; o >>= 1) sum += __shfl_xor_sync(0xffffffffu, sum, o);
            __syncthreads();
            attn_s[tid] = e;
            if (lane == 0) red_s[wid] = sum;
            __syncthreads();
            sum = 0.f;
#pragma unroll
            for (int w = 0; w < 8; w++) sum += red_s[w];
            float inv = __fdividef(1.0f, sum);

            int h = hbase + tid;
            const float* hv = g_hidden + ((size_t)(b * SS) << 10) + h;
            float a0 = 0.f, a1 = 0.f, a2 = 0.f, a3 = 0.f;
            for (int s = 0; s < SS; s += 4) {
                a0 = fmaf(attn_s[s],     hv[(size_t)s << 10],       a0);
                a1 = fmaf(attn_s[s + 1], hv[(size_t)(s + 1) << 10], a1);
                a2 = fmaf(attn_s[s + 2], hv[(size_t)(s + 2) << 10], a2);
                a3 = fmaf(attn_s[s + 3], hv[(size_t)(s + 3) << 10], a3);
            }
            float acc = ((a0 + a1) + (a2 + a3)) * inv;
            g_xpairf[(EE + h) * 16 + (b & 7) * 2 + (b >> 3)] = acc;
            g_Z[((size_t)(t * BB + b) << 11) + HH + h] = acc;
        }
        float4 wa0, wb0, wa1, wb1;
        if (bid < 128) {
            wa0 = *(const float4*)(Wp);
            wb0 = *(const float4*)(Wp + 4);
            wa1 = *(const float4*)(Wp + 64);
            wb1 = *(const float4*)(Wp + 68);
        }
        gbar();

        if (bid < 128) {
            ulonglong2 xv0 = __ldcg((const ulonglong2*)(Xb));
            ulonglong2 xv1 = __ldcg((const ulonglong2*)(Xb + 1024));
            ull acA = 0ull, acB = 0ull;
            for (int c = 0; c < 56; c += 2) {
                __syncthreads();
                *(float4*)&w_s[sn][sk] = wa0;
                *(float4*)&w_s[sn][sk + 4] = wb0;
                x2_s[xp][xk] = xv0.x;
                x2_s[xp + 1][xk] = xv0.y;
                __syncthreads();
                {
                    int cn = (c + 2 < 56) ? c + 2 : 54;
                    wa0 = *(const float4*)(Wp + cn * 64);
                    wb0 = *(const float4*)(Wp + cn * 64 + 4);
                    xv0 = __ldcg((const ulonglong2*)(Xb + cn * 1024 + (cn >= 40 ? hof : 0)));
                }
#pragma unroll
                for (int kg = 0; kg < 16; kg++) {
                    float4 w = *(const float4*)&w_s[nl][kg * 4];
                    ulonglong2 xa = *(const ulonglong2*)&x2_s[pr][kg * 4];
                    ulonglong2 xc = *(const ulonglong2*)&x2_s[pr][kg * 4 + 2];
                    ffma2(acA, dup2(w.x), xa.x);
                    ffma2(acB, dup2(w.y), xa.y);
                    ffma2(acA, dup2(w.z), xc.x);
                    ffma2(acB, dup2(w.w), xc.y);
                }
                __syncthreads();
                *(float4*)&w_s[sn][sk] = wa1;
                *(float4*)&w_s[sn][sk + 4] = wb1;
                x2_s[xp][xk] = xv1.x;
                x2_s[xp + 1][xk] = xv1.y;
                __syncthreads();
                {
                    int cn = (c + 3 < 56) ? c + 3 : 55;
                    wa1 = *(const float4*)(Wp + cn * 64);
                    wb1 = *(const float4*)(Wp + cn * 64 + 4);
                    xv1 = __ldcg((const ulonglong2*)(Xb + cn * 1024 + (cn >= 40 ? hof : 0)));
                }
#pragma unroll
                for (int kg = 0; kg < 16; kg++) {
                    float4 w = *(const float4*)&w_s[nl][kg * 4];
                    ulonglong2 xa = *(const ulonglong2*)&x2_s[pr][kg * 4];
                    ulonglong2 xc = *(const ulonglong2*)&x2_s[pr][kg * 4 + 2];
                    ffma2(acA, dup2(w.x), xa.x);
                    ffma2(acB, dup2(w.y), xa.y);
                    ffma2(acA, dup2(w.z), xc.x);
                    ffma2(acB, dup2(w.w), xc.y);
                }
            }
            {
                float2 ga = up2(acA), gb = up2(acB);
                float bsum = g_bias_sum[bid * 32 + nl];
                gsm[nl][pr]     = ga.x + gb.x + bsum;
                gsm[nl][pr + 8] = ga.y + gb.y + bsum;
            }
            __syncthreads();
            if (tid < 128) {
                int b = tid & 15, hl = tid >> 4;
                float ig = gsm[hl][b];
                float fg = gsm[8 + hl][b];
                float gg = gsm[16 + hl][b];
                float og = gsm[24 + hl][b];
                float cn = fast_sig(fg) * creg + fast_sig(ig) * fast_tanh(gg);
                float hn = fast_sig(og) * fast_tanh(cn);
                creg = cn;
                int hg = bid * 8 + hl;
                int idx = (b << 10) + hg;
                g_h[idx] = hn;
                g_xpairf[(XLEN + (((t + 1) & 1) << 10) + hg) * 16 + (b & 7) * 2 + (b >> 3)] = hn;
                g_Z[((size_t)(t * BB + b) << 11) + hg] = hn;
                g_hW[idx] = 0.0f;
            }
        }
        gbar();
    }
}

// ---------------- host launch ----------------
extern "C" void kernel_launch(void* const* d_in, const int* in_sizes, int n_in,
                              void* d_out, int out_size)
{
    (void)in_sizes; (void)n_in; (void)out_size;
    const int*   inp    = (const int*)  d_in[0];
    const float* VQ     = (const float*)d_in[1];
    const float* embedW = (const float*)d_in[2];
    const float* transW = (const float*)d_in[3];
    const float* attnW  = (const float*)d_in[4];
    const float* attnb  = (const float*)d_in[5];
    const float* v      = (const float*)d_in[6];
    const float* W_ih   = (const float*)d_in[7];
    const float* W_hh   = (const float*)d_in[8];
    const float* b_ih   = (const float*)d_in[9];
    const float* b_hh   = (const float*)d_in[10];
    const float* predW  = (const float*)d_in[11];
    float* out = (float*)d_out;

    float *p_hidden, *p_hsproj, *p_Z;
    __nv_bfloat16 *pBhi, *pBlo, *pZhi, *pZlo;
    cudaGetSymbolAddress((void**)&p_hidden, g_hidden);
    cudaGetSymbolAddress((void**)&p_hsproj, g_hsproj);
    cudaGetSymbolAddress((void**)&p_Z,      g_Z);
    cudaGetSymbolAddress((void**)&pBhi,     g_Bhi);
    cudaGetSymbolAddress((void**)&pBlo,     g_Blo);
    cudaGetSymbolAddress((void**)&pZhi,     g_Zhi);
    cudaGetSymbolAddress((void**)&pZlo,     g_Zlo);

    cudaFuncSetAttribute(k_logits_mma, cudaFuncAttributeMaxDynamicSharedMemorySize, MMA_SMEM);

    k_prep<<<2048, 256>>>(inp, embedW, W_ih, W_hh, b_ih, b_hh, out);
    k_biggemm<0><<<dim3(32, 16), 256>>>(VQ, DQD, transW, DQD, 0, nullptr,
                                        p_hidden, HH, BB * SS, DQD);
    k_biggemm<1><<<dim3(32, 16), 256>>>(p_hidden, HH, attnW, 2 * HH, HH, attnb,
                                        p_hsproj, HH, BB * SS, HH);
    k_init_h<<<64, 256>>>();
    // split predW into bf16 hi/lo (independent of recurrence)
    k_cvt<<<2048, 256>>>(predW, pBhi, pBlo, (size_t)VV * 2 * HH, (size_t)VV * 2 * HH);

    // entire 255-step recurrence: ONE kernel
    k_recur<<<NBLK, 256>>>(attnW, v);

    // split Z into bf16 hi/lo (pad rows 4080..4095 with zeros)
    k_cvt<<<2048, 256>>>(p_Z, pZhi, pZlo, (size_t)TT * BB * 2 * HH, (size_t)4096 * 2 * HH);

    // tensor-core logits GEMM (4080 x 32000, K=2048), 3-term bf16 split, fp32 accum
    k_logits_mma<<<dim3(32, 250), 256, MMA_SMEM>>>(pZhi, pZlo, pBhi, pBlo, out);
}

// round 17
// speedup vs baseline: 1.5506x; 1.0025x over previous
#include <cuda_runtime.h>
#include <cuda_bf16.h>

#define BB 16
#define SS 256
#define VV 32000
#define HH 1024
#define EE 512
#define DQD 512
#define TT 255
#define KG 3584
#define G4 4096
#define XLEN 2560
#define NBLK 148

typedef unsigned long long ull;

// ---------------- device scratch ----------------
__device__ __align__(16) float g_hidden[BB*SS*HH];
__device__ __align__(16) float g_hsproj[BB*SS*HH];
__device__ __align__(16) float g_h[BB*HH];
__device__ __align__(16) float g_c[BB*HH];
__device__ __align__(16) float g_hW[BB*HH];
__device__ __align__(16) float g_score[BB*SS];
__device__ __align__(16) float g_Wcat[(size_t)G4*KG];   // rows reordered by colmap
__device__ __align__(16) float g_bias_sum[G4];          // reordered
__device__ __align__(16) float g_we[(size_t)TT*BB*EE];
__device__ __align__(16) float g_Z[(size_t)TT*BB*2*HH];
// x pair table; h segment (k in [2560,3584)) double-buffered
__device__ __align__(16) float g_xpairf[(KG + HH) * 16];
__device__ unsigned g_cnt = 0;
__device__ volatile unsigned g_gen = 0;

// bf16 split operands for the tensor-core logits GEMM
__device__ __align__(16) __nv_bfloat16 g_Bhi[(size_t)VV*2*HH];
__device__ __align__(16) __nv_bfloat16 g_Blo[(size_t)VV*2*HH];
__device__ __align__(16) __nv_bfloat16 g_Zhi[(size_t)4096*2*HH];   // padded rows
__device__ __align__(16) __nv_bfloat16 g_Zlo[(size_t)4096*2*HH];

// ---------------- f32x2 helpers ----------------
__device__ __forceinline__ void ffma2(ull& d, ull a, ull b) {
    asm("fma.rn.f32x2 %0, %1, %2, %0;" : "+l"(d) : "l"(a), "l"(b));
}
__device__ __forceinline__ ull dup2(float x) {
    ull r; asm("mov.b64 %0, {%1, %1};" : "=l"(r) : "f"(x)); return r;
}
__device__ __forceinline__ float2 up2(ull u) {
    float2 f; asm("mov.b64 {%0, %1}, %2;" : "=f"(f.x), "=f"(f.y) : "l"(u)); return f;
}

__device__ __forceinline__ float fast_tanh(float x) {
    float e = __expf(2.0f * x);
    return 1.0f - __fdividef(2.0f, e + 1.0f);
}
__device__ __forceinline__ float fast_sig(float x) {
    return __fdividef(1.0f, 1.0f + __expf(-x));
}

__device__ __forceinline__ unsigned smem_u32(const void* p) {
    unsigned a;
    asm("{ .reg .u64 t; cvta.to.shared.u64 t, %1; cvt.u32.u64 %0, t; }" : "=r"(a) : "l"(p));
    return a;
}

// ---------------- mma.sync helpers (sm_80+ PTX, compiles for compute_103) ----------------
#define LDSM4(r, a)                                                                   \
    asm volatile("ldmatrix.sync.aligned.m8n8.x4.shared.b16 {%0,%1,%2,%3}, [%4];"      \
        : "=r"((r)[0]), "=r"((r)[1]), "=r"((r)[2]), "=r"((r)[3]) : "r"(a))
#define LDSM2(r, a)                                                                   \
    asm volatile("ldmatrix.sync.aligned.m8n8.x2.shared.b16 {%0,%1}, [%2];"            \
        : "=r"((r)[0]), "=r"((r)[1]) : "r"(a))
#define MMA_BF16(d, a, b)                                                             \
    asm volatile("mma.sync.aligned.m16n8k16.row.col.f32.bf16.bf16.f32 "               \
        "{%0,%1,%2,%3}, {%4,%5,%6,%7}, {%8,%9}, {%0,%1,%2,%3};"                       \
        : "+f"((d)[0]), "+f"((d)[1]), "+f"((d)[2]), "+f"((d)[3])                      \
        : "r"((a)[0]), "r"((a)[1]), "r"((a)[2]), "r"((a)[3]), "r"((b)[0]), "r"((b)[1]))

// column reorder: block bid owns cols [bid*32, bid*32+32) = gates [i,f,g,o] x h in [bid*8, bid*8+8)
__device__ __forceinline__ int colmap(int c) {
    int g = (c & 31) >> 3, hl = c & 7, blk = c >> 5;
    return g * HH + blk * 8 + hl;
}

// ---------------- prep ----------------
__global__ void k_prep(const int* __restrict__ inp, const float* __restrict__ embedW,
                       const float* __restrict__ W_ih, const float* __restrict__ W_hh,
                       const float* __restrict__ b_ih, const float* __restrict__ b_hh,
                       float* __restrict__ out)
{
    const long long N1 = (long long)G4 * KG;
    const long long N2 = N1 + G4;
    const long long N3 = N2 + (long long)TT * BB * EE;
    const long long N4 = N3 + (long long)BB * VV;
    for (long long i = (long long)blockIdx.x * blockDim.x + threadIdx.x;
         i < N4; i += (long long)gridDim.x * blockDim.x) {
        if (i < N1) {
            int c = (int)(i / KG), k = (int)(i % KG);
            int n = colmap(c);
            g_Wcat[i] = (k < XLEN) ? W_ih[(long long)n * XLEN + k]
                                   : W_hh[(long long)n * HH + (k - XLEN)];
        } else if (i < N2) {
            int c = (int)(i - N1);
            int n = colmap(c);
            g_bias_sum[c] = b_ih[n] + b_hh[n];
        } else if (i < N3) {
            long long j = i - N2;
            int t = (int)(j / (BB * EE));
            int r = (int)(j % (BB * EE));
            int b = r / EE, e = r % EE;
            int tok = inp[b * SS + t];
            g_we[j] = embedW[(long long)tok * EE + e];
        } else {
            long long j = i - N3;
            int b = (int)(j / VV);
            int vv = (int)(j % VV);
            out[(long long)b * SS * VV + vv] = 0.0f;
        }
    }
}

__global__ void k_init_h()
{
    int idx = blockIdx.x * blockDim.x + threadIdx.x;   // 16384
    int b = idx >> 10, h = idx & 1023;
    float c0 = g_hidden[((b * SS + (SS - 1)) << 10) + h];
    g_c[idx] = c0;
    float h0 = tanhf(c0);
    g_h[idx] = h0;
    g_hW[idx] = 0.0f;
    int sl = (b & 7) * 2 + (b >> 3);
    g_xpairf[(EE + HH + h) * 16 + sl] = h0;   // static h0 segment
    g_xpairf[(XLEN + h) * 16 + sl]    = h0;   // h buffer 0: step 0 reads h_0 here
}

// ---------------- fp32 -> bf16 hi/lo split ----------------
__global__ void k_cvt(const float* __restrict__ src, __nv_bfloat16* __restrict__ hi,
                      __nv_bfloat16* __restrict__ lo, size_t n_src, size_t n_tot)
{
    for (size_t i = (size_t)blockIdx.x * blockDim.x + threadIdx.x; i < n_tot;
         i += (size_t)gridDim.x * blockDim.x) {
        float x = (i < n_src) ? src[i] : 0.0f;
        __nv_bfloat16 h = __float2bfloat16(x);
        hi[i] = h;
        lo[i] = __float2bfloat16(x - __bfloat162float(h));
    }
}

// ---------------- big tiled fp32 GEMM (verified; precompute only) ----------------
template<int BIAS_EN>
__global__ __launch_bounds__(256)
void k_biggemm(const float* __restrict__ A, int lda,
               const float* __restrict__ W, int ldw, int woff,
               const float* __restrict__ bias,
               float* __restrict__ C, int ldc, int M, int K)
{
    __shared__ float As[16][132];
    __shared__ float Bs[16][68];
    int tid = threadIdx.x;
    int m0 = blockIdx.x * 128;
    int n0 = blockIdx.y * 64;
    int ar  = tid >> 1;
    int akc = (tid & 1) * 8;
    int wn  = tid >> 2;
    int wkc = (tid & 3) * 4;
    int tx  = tid & 15;
    int ty  = tid >> 4;

    float acc[8][4];
#pragma unroll
    for (int i = 0; i < 8; i++)
#pragma unroll
        for (int j = 0; j < 4; j++) acc[i][j] = 0.0f;

    const float* Arow = A + (size_t)(m0 + ar) * lda;
    const float* Wrow = W + (size_t)(n0 + wn) * ldw + woff;

    for (int k0 = 0; k0 < K; k0 += 16) {
        float4 av0 = *(const float4*)(Arow + k0 + akc);
        float4 av1 = *(const float4*)(Arow + k0 + akc + 4);
        float4 wv  = *(const float4*)(Wrow + k0 + wkc);
        __syncthreads();
        As[akc + 0][ar] = av0.x; As[akc + 1][ar] = av0.y;
        As[akc + 2][ar] = av0.z; As[akc + 3][ar] = av0.w;
        As[akc + 4][ar] = av1.x; As[akc + 5][ar] = av1.y;
        As[akc + 6][ar] = av1.z; As[akc + 7][ar] = av1.w;
        Bs[wkc + 0][wn] = wv.x;  Bs[wkc + 1][wn] = wv.y;
        Bs[wkc + 2][wn] = wv.z;  Bs[wkc + 3][wn] = wv.w;
        __syncthreads();
#pragma unroll
        for (int kk = 0; kk < 16; kk++) {
            float4 a0 = *(const float4*)&As[kk][ty * 8];
            float4 a1 = *(const float4*)&As[kk][ty * 8 + 4];
            float4 bv = *(const float4*)&Bs[kk][tx * 4];
            float ra[8] = {a0.x, a0.y, a0.z, a0.w, a1.x, a1.y, a1.z, a1.w};
            float rb[4] = {bv.x, bv.y, bv.z, bv.w};
#pragma unroll
            for (int i = 0; i < 8; i++)
#pragma unroll
                for (int j = 0; j < 4; j++)
                    acc[i][j] = fmaf(ra[i], rb[j], acc[i][j]);
        }
    }
#pragma unroll
    for (int i = 0; i < 8; i++) {
        int m = m0 + ty * 8 + i;
        float4 r;
        r.x = acc[i][0]; r.y = acc[i][1]; r.z = acc[i][2]; r.w = acc[i][3];
        if (BIAS_EN) {
            int n = n0 + tx * 4;
            r.x += bias[n]; r.y += bias[n + 1]; r.z += bias[n + 2]; r.w += bias[n + 3];
        }
        *(float4*)(C + (size_t)m * ldc + n0 + tx * 4) = r;
    }
}

// ---------------- tensor-core logits GEMM: mma.sync bf16 3-term split (verified R15) ----
#define LDS_STRIDE 80
#define TILE_B (128 * LDS_STRIDE)
#define STAGE_B (4 * TILE_B)
#define MMA_SMEM (2 * STAGE_B)

__global__ __launch_bounds__(256)
void k_logits_mma(const __nv_bfloat16* __restrict__ Ahi, const __nv_bfloat16* __restrict__ Alo,
                  const __nv_bfloat16* __restrict__ Bhi, const __nv_bfloat16* __restrict__ Blo,
                  float* __restrict__ C)
{
    extern __shared__ char sm[];
    const unsigned sb = smem_u32(sm);
    const int tid = threadIdx.x, lane = tid & 31, wid = tid >> 5;
    const int wm = wid & 1, wn = wid >> 1;
    const int m0 = blockIdx.x * 128;
    const int n0 = blockIdx.y * 128;

    const __nv_bfloat16* gsrc[4] = {
        Ahi + (size_t)m0 * 2048, Alo + (size_t)m0 * 2048,
        Bhi + (size_t)n0 * 2048, Blo + (size_t)n0 * 2048 };

    float acc[4][4][4];
#pragma unroll
    for (int i = 0; i < 4; i++)
#pragma unroll
        for (int j = 0; j < 4; j++)
#pragma unroll
            for (int q = 0; q < 4; q++) acc[i][j][q] = 0.0f;

    const int r0 = tid >> 2,  s0 = tid & 3;
    const int r1 = (256 + tid) >> 2, s1 = tid & 3;

    float4 v[8];
    auto ldchunk = [&](int c) {
#pragma unroll
        for (int t = 0; t < 4; t++) {
            const __nv_bfloat16* g = gsrc[t] + (size_t)c * 32;
            v[t * 2 + 0] = *(const float4*)(g + (size_t)r0 * 2048 + s0 * 8);
            v[t * 2 + 1] = *(const float4*)(g + (size_t)r1 * 2048 + s1 * 8);
        }
    };
    auto stchunk = [&](int buf) {
        char* base = sm + buf * STAGE_B;
#pragma unroll
        for (int t = 0; t < 4; t++) {
            *(float4*)(base + t * TILE_B + r0 * LDS_STRIDE + s0 * 16) = v[t * 2 + 0];
            *(float4*)(base + t * TILE_B + r1 * LDS_STRIDE + s1 * 16) = v[t * 2 + 1];
        }
    };

    ldchunk(0);
    stchunk(0);
    __syncthreads();

    for (int c = 0; c < 64; c++) {
        if (c < 63) ldchunk(c + 1);
        const unsigned sbase = sb + (c & 1) * STAGE_B;
#pragma unroll
        for (int kf = 0; kf < 2; kf++) {
            unsigned ah[4][4], al[4][4], bh[4][2], bl[4][2];
#pragma unroll
            for (int mf = 0; mf < 4; mf++) {
                unsigned ra = (unsigned)((wm * 64 + mf * 16 + (lane & 15)) * LDS_STRIDE
                                         + kf * 32 + ((lane >> 4) & 1) * 16);
                LDSM4(ah[mf], sbase + 0 * TILE_B + ra);
                LDSM4(al[mf], sbase + 1 * TILE_B + ra);
            }
#pragma unroll
            for (int nf = 0; nf < 4; nf++) {
                unsigned rb = (unsigned)((wn * 32 + nf * 8 + (lane & 7)) * LDS_STRIDE
                                         + kf * 32 + ((lane >> 3) & 1) * 16);
                LDSM2(bh[nf], sbase + 2 * TILE_B + rb);
                LDSM2(bl[nf], sbase + 3 * TILE_B + rb);
            }
#pragma unroll
            for (int mf = 0; mf < 4; mf++)
#pragma unroll
                for (int nf = 0; nf < 4; nf++) {
                    MMA_BF16(acc[mf][nf], ah[mf], bh[nf]);
                    MMA_BF16(acc[mf][nf], al[mf], bh[nf]);
                    MMA_BF16(acc[mf][nf], ah[mf], bl[nf]);
                }
        }
        if (c < 63) {
            __syncthreads();
            stchunk((c + 1) & 1);
            __syncthreads();
        }
    }

#pragma unroll
    for (int mf = 0; mf < 4; mf++)
#pragma unroll
        for (int i = 0; i < 2; i++) {
            int m = m0 + wm * 64 + mf * 16 + (lane >> 2) + i * 8;
            if (m < TT * BB) {
                int trow = m >> 4, b = m & 15;
                float* dst = C + (size_t)(b * SS + trow + 1) * VV
                             + n0 + wn * 32 + (lane & 3) * 2;
#pragma unroll
                for (int nf = 0; nf < 4; nf++) {
                    float2 w;
                    w.x = acc[mf][nf][i * 2 + 0];
                    w.y = acc[mf][nf][i * 2 + 1];
                    *(float2*)(dst + nf * 8) = w;
                }
            }
        }
}

// ---------------- atomic grid barrier (verified) ----------------
__device__ __forceinline__ void gbar() {
    __syncthreads();
    if (threadIdx.x == 0) {
        __threadfence();
        unsigned g = g_gen;
        if (atomicAdd(&g_cnt, 1u) == NBLK - 1) {
            g_cnt = 0;
            __threadfence();
            g_gen = g + 1;
        } else {
            while (g_gen == g) __nanosleep(64);
        }
        __threadfence();
    }
    __syncthreads();
}

// ---------------- persistent recurrence ----------------
__global__ __launch_bounds__(256)
void k_recur(const float* __restrict__ attnW, const float* __restrict__ v)
{
    __shared__ __align__(16) float w_s[32][68];
    __shared__ __align__(16) ull  x2_s[8][66];
    __shared__ float gsm[32][16];
    __shared__ float aw_s[8][32][4];
    __shared__ float aa_s[16][36];
    __shared__ float attn_s[SS];
    __shared__ float red_s[8];

    const int bid = blockIdx.x;
    const int tid = threadIdx.x;
    const int lane = tid & 31;
    const int wid = tid >> 5;
    const int n_l = tid & 31, bq = tid >> 5;
    const int wn = tid >> 3, wk = (tid & 7) * 4;
    const int kk = tid & 31, bb = tid >> 5;
    // phase D compute ids: warp = 4 DISJOINT n-cols x 8 pairs (W reads become
    // 8-way broadcasts: 64B distinct/kg/warp instead of 512B -> crossbar 8x lighter)
    const int nl = wid * 4 + (lane >> 3);    // 0..31, disjoint col set per warp
    const int pr = lane & 7;                 // 0..7
    const int sn = tid >> 3;
    const int sk = (tid & 7) * 8;
    const int xk = tid >> 2;
    const int xp = (tid & 3) * 2;

    float creg = 0.0f;
    if (bid < 128 && tid < 128)
        creg = g_c[((tid & 15) << 10) + bid * 8 + (tid >> 4)];

    const float* Wp = g_Wcat + (size_t)(bid * 32 + sn) * KG + sk;
    const float* Xb = g_xpairf + tid * 4;

    for (int t = 0; t < TT; t++) {
        const int hof = (t & 1) << 14;

        if (bid < 128) {
            int an0 = (bid & 31) * 32;
            int kbeg = (bid >> 5) * 256;
            int kend = kbeg + 256;
            float acc0 = 0.f, acc1 = 0.f;
            const float* Whp = attnW + (size_t)(an0 + wn) * (2 * HH) + wk;
            float4 wv = *(const float4*)(Whp + kbeg);
            float a0 = __ldcg(&g_h[(bb << 10) + kbeg + kk]);
            float a1 = __ldcg(&g_h[((bb + 8) << 10) + kbeg + kk]);
            for (int k0 = kbeg; k0 < kend; k0 += 32) {
                __syncthreads();
                *(float4*)&aw_s[wk >> 2][wn][0] = wv;
                aa_s[bq][kk] = a0;
                aa_s[bq + 8][kk] = a1;
                __syncthreads();
                int kn = k0 + 32;
                if (kn < kend) {
                    wv = *(const float4*)(Whp + kn);
                    a0 = __ldcg(&g_h[(bb << 10) + kn + kk]);
                    a1 = __ldcg(&g_h[((bb + 8) << 10) + kn + kk]);
                }
#pragma unroll
                for (int kg = 0; kg < 8; kg++) {
                    float4 w4 = *(const float4*)&aw_s[kg][n_l][0];
                    float4 A0 = *(const float4*)&aa_s[bq][kg * 4];
                    float4 A1 = *(const float4*)&aa_s[bq + 8][kg * 4];
                    acc0 = fmaf(w4.x, A0.x, acc0); acc0 = fmaf(w4.y, A0.y, acc0);
                    acc0 = fmaf(w4.z, A0.z, acc0); acc0 = fmaf(w4.w, A0.w, acc0);
                    acc1 = fmaf(w4.x, A1.x, acc1); acc1 = fmaf(w4.y, A1.y, acc1);
                    acc1 = fmaf(w4.z, A1.z, acc1); acc1 = fmaf(w4.w, A1.w, acc1);
                }
            }
            atomicAdd(&g_hW[(bq << 10) + an0 + n_l], acc0);
            atomicAdd(&g_hW[((bq + 8) << 10) + an0 + n_l], acc1);
        } else {
            for (int j = (bid - 128) * 256 + tid; j < BB * EE; j += 20 * 256) {
                int k = j >> 4, b = j & 15;
                g_xpairf[k * 16 + (b & 7) * 2 + (b >> 3)] =
                    g_we[((size_t)t * BB + b) * EE + k];
            }
        }
        gbar();

        for (int p = bid * 8 + wid; p < BB * SS; p += NBLK * 8) {
            int b = p >> 8;
            const float* hsp = g_hsproj + ((size_t)p << 10);
            const float* hw = g_hW + (b << 10);
            float acc = 0.f;
#pragma unroll 8
            for (int i = 0; i < 32; i++) {
                int k = lane + (i << 5);
                acc += v[k] * fast_tanh(__ldcg(&hw[k]) + hsp[k]);
            }
#pragma unroll
            for (int o = 16; o > 0; o >>= 1) acc += __shfl_xor_sync(0xffffffffu, acc, o);
            if (lane == 0) g_score[p] = acc;
        }
        gbar();

        if (bid < 64) {
            int b = bid >> 2;
            int hbase = (bid & 3) * 256;
            float sc = __ldcg(&g_score[b * SS + tid]);
            float m = sc;
#pragma unroll
            for (int o = 16; o > 0; o >>= 1) m = fmaxf(m, __shfl_xor_sync(0xffffffffu, m, o));
            if (lane == 0) red_s[wid] = m;
            __syncthreads();
            m = red_s[0];
#pragma unroll
            for (int w = 1; w < 8; w++) m = fmaxf(m, red_s[w]);
            float e = __expf(sc - m);
            float sum = e;
#pragma unroll
            for (int o = 16; o > 0; o >>= 1) sum += __shfl_xor_sync(0xffffffffu, sum, o);
            __syncthreads();
            attn_s[tid] = e;
            if (lane == 0) red_s[wid] = sum;
            __syncthreads();
            sum = 0.f;
#pragma unroll
            for (int w = 0; w < 8; w++) sum += red_s[w];
            float inv = __fdividef(1.0f, sum);

            int h = hbase + tid;
            const float* hv = g_hidden + ((size_t)(b * SS) << 10) + h;
            float a0 = 0.f, a1 = 0.f, a2 = 0.f, a3 = 0.f;
            for (int s = 0; s < SS; s += 4) {
                a0 = fmaf(attn_s[s],     hv[(size_t)s << 10],       a0);
                a1 = fmaf(attn_s[s + 1], hv[(size_t)(s + 1) << 10], a1);
                a2 = fmaf(attn_s[s + 2], hv[(size_t)(s + 2) << 10], a2);
                a3 = fmaf(attn_s[s + 3], hv[(size_t)(s + 3) << 10], a3);
            }
            float acc = ((a0 + a1) + (a2 + a3)) * inv;
            g_xpairf[(EE + h) * 16 + (b & 7) * 2 + (b >> 3)] = acc;
            g_Z[((size_t)(t * BB + b) << 11) + HH + h] = acc;
        }
        float4 wa0, wb0, wa1, wb1;
        if (bid < 128) {
            wa0 = *(const float4*)(Wp);
            wb0 = *(const float4*)(Wp + 4);
            wa1 = *(const float4*)(Wp + 64);
            wb1 = *(const float4*)(Wp + 68);
        }
        gbar();

        if (bid < 128) {
            ulonglong2 xv0 = __ldcg((const ulonglong2*)(Xb));
            ulonglong2 xv1 = __ldcg((const ulonglong2*)(Xb + 1024));
            ull acA = 0ull, acB = 0ull;
            for (int c = 0; c < 56; c += 2) {
                __syncthreads();
                *(float4*)&w_s[sn][sk] = wa0;
                *(float4*)&w_s[sn][sk + 4] = wb0;
                x2_s[xp][xk] = xv0.x;
                x2_s[xp + 1][xk] = xv0.y;
                __syncthreads();
                {
                    int cn = (c + 2 < 56) ? c + 2 : 54;
                    wa0 = *(const float4*)(Wp + cn * 64);
                    wb0 = *(const float4*)(Wp + cn * 64 + 4);
                    xv0 = __ldcg((const ulonglong2*)(Xb + cn * 1024 + (cn >= 40 ? hof : 0)));
                }
#pragma unroll
                for (int kg = 0; kg < 16; kg++) {
                    float4 w = *(const float4*)&w_s[nl][kg * 4];
                    ulonglong2 xa = *(const ulonglong2*)&x2_s[pr][kg * 4];
                    ulonglong2 xc = *(const ulonglong2*)&x2_s[pr][kg * 4 + 2];
                    ffma2(acA, dup2(w.x), xa.x);
                    ffma2(acB, dup2(w.y), xa.y);
                    ffma2(acA, dup2(w.z), xc.x);
                    ffma2(acB, dup2(w.w), xc.y);
                }
                __syncthreads();
                *(float4*)&w_s[sn][sk] = wa1;
                *(float4*)&w_s[sn][sk + 4] = wb1;
                x2_s[xp][xk] = xv1.x;
                x2_s[xp + 1][xk] = xv1.y;
                __syncthreads();
                {
                    int cn = (c + 3 < 56) ? c + 3 : 55;
                    wa1 = *(const float4*)(Wp + cn * 64);
                    wb1 = *(const float4*)(Wp + cn * 64 + 4);
                    xv1 = __ldcg((const ulonglong2*)(Xb + cn * 1024 + (cn >= 40 ? hof : 0)));
                }
#pragma unroll
                for (int kg = 0; kg < 16; kg++) {
                    float4 w = *(const float4*)&w_s[nl][kg * 4];
                    ulonglong2 xa = *(const ulonglong2*)&x2_s[pr][kg * 4];
                    ulonglong2 xc = *(const ulonglong2*)&x2_s[pr][kg * 4 + 2];
                    ffma2(acA, dup2(w.x), xa.x);
                    ffma2(acB, dup2(w.y), xa.y);
                    ffma2(acA, dup2(w.z), xc.x);
                    ffma2(acB, dup2(w.w), xc.y);
                }
            }
            {
                float2 ga = up2(acA), gb = up2(acB);
                float bsum = g_bias_sum[bid * 32 + nl];
                gsm[nl][pr]     = ga.x + gb.x + bsum;
                gsm[nl][pr + 8] = ga.y + gb.y + bsum;
            }
            __syncthreads();
            if (tid < 128) {
                int b = tid & 15, hl = tid >> 4;
                float ig = gsm[hl][b];
                float fg = gsm[8 + hl][b];
                float gg = gsm[16 + hl][b];
                float og = gsm[24 + hl][b];
                float cn = fast_sig(fg) * creg + fast_sig(ig) * fast_tanh(gg);
                float hn = fast_sig(og) * fast_tanh(cn);
                creg = cn;
                int hg = bid * 8 + hl;
                int idx = (b << 10) + hg;
                g_h[idx] = hn;
                g_xpairf[(XLEN + (((t + 1) & 1) << 10) + hg) * 16 + (b & 7) * 2 + (b >> 3)] = hn;
                g_Z[((size_t)(t * BB + b) << 11) + hg] = hn;
                g_hW[idx] = 0.0f;
            }
        }
        gbar();
    }
}

// ---------------- host launch ----------------
extern "C" void kernel_launch(void* const* d_in, const int* in_sizes, int n_in,
                              void* d_out, int out_size)
{
    (void)in_sizes; (void)n_in; (void)out_size;
    const int*   inp    = (const int*)  d_in[0];
    const float* VQ     = (const float*)d_in[1];
    const float* embedW = (const float*)d_in[2];
    const float* transW = (const float*)d_in[3];
    const float* attnW  = (const float*)d_in[4];
    const float* attnb  = (const float*)d_in[5];
    const float* v      = (const float*)d_in[6];
    const float* W_ih   = (const float*)d_in[7];
    const float* W_hh   = (const float*)d_in[8];
    const float* b_ih   = (const float*)d_in[9];
    const float* b_hh   = (const float*)d_in[10];
    const float* predW  = (const float*)d_in[11];
    float* out = (float*)d_out;

    float *p_hidden, *p_hsproj, *p_Z;
    __nv_bfloat16 *pBhi, *pBlo, *pZhi, *pZlo;
    cudaGetSymbolAddress((void**)&p_hidden, g_hidden);
    cudaGetSymbolAddress((void**)&p_hsproj, g_hsproj);
    cudaGetSymbolAddress((void**)&p_Z,      g_Z);
    cudaGetSymbolAddress((void**)&pBhi,     g_Bhi);
    cudaGetSymbolAddress((void**)&pBlo,     g_Blo);
    cudaGetSymbolAddress((void**)&pZhi,     g_Zhi);
    cudaGetSymbolAddress((void**)&pZlo,     g_Zlo);

    cudaFuncSetAttribute(k_logits_mma, cudaFuncAttributeMaxDynamicSharedMemorySize, MMA_SMEM);

    k_prep<<<2048, 256>>>(inp, embedW, W_ih, W_hh, b_ih, b_hh, out);
    k_biggemm<0><<<dim3(32, 16), 256>>>(VQ, DQD, transW, DQD, 0, nullptr,
                                        p_hidden, HH, BB * SS, DQD);
    k_biggemm<1><<<dim3(32, 16), 256>>>(p_hidden, HH, attnW, 2 * HH, HH, attnb,
                                        p_hsproj, HH, BB * SS, HH);
    k_init_h<<<64, 256>>>();
    // split predW into bf16 hi/lo (independent of recurrence)
    k_cvt<<<2048, 256>>>(predW, pBhi, pBlo, (size_t)VV * 2 * HH, (size_t)VV * 2 * HH);

    // entire 255-step recurrence: ONE kernel
    k_recur<<<NBLK, 256>>>(attnW, v);

    // split Z into bf16 hi/lo (pad rows 4080..4095 with zeros)
    k_cvt<<<2048, 256>>>(p_Z, pZhi, pZlo, (size_t)TT * BB * 2 * HH, (size_t)4096 * 2 * HH);

    // tensor-core logits GEMM (4080 x 32000, K=2048), 3-term bf16 split, fp32 accum
    k_logits_mma<<<dim3(32, 250), 256, MMA_SMEM>>>(pZhi, pZlo, pBhi, pBlo, out);
}